// round 8
// baseline (speedup 1.0000x reference)
#include <cuda_runtime.h>
#include <cuda_fp16.h>
#include <math.h>
#include <stdint.h>

#define B 2
#define S 2048
#define D 768
#define H 12
#define E 64
#define BS (B*S)   // 4096
#define HB (H*B)   // 24
#define XN (BS*D)
#define HED (H*E*D)

// ---- scratch (static device globals; no runtime allocation) ----
__device__ __align__(16) __half g_x_hi[(size_t)BS * D];
__device__ __align__(16) __half g_x_lo[(size_t)BS * D];
__device__ __align__(16) __half g_wt_hi[(size_t)3 * H * E * D]; // [which][h*E+e][k]
__device__ __align__(16) __half g_wt_lo[(size_t)3 * H * E * D];
__device__ __align__(16) __half g_wo_hi[(size_t)D * D];         // [n][k]
__device__ __align__(16) __half g_wo_lo[(size_t)D * D];
__device__ __align__(16) __half g_qkvb_hi[(size_t)3 * H * BS * E]; // [which][h][b*S+s][e]
__device__ __align__(16) __half g_qkvb_lo[(size_t)3 * H * BS * E];
__device__ __align__(16) __half g_att_hi[(size_t)BS * D];       // [b*S+s][h*E+e]
__device__ __align__(16) __half g_att_lo[(size_t)BS * D];
// split-KV partials: [half][hb][row][e] fp32, plus running max / sum per row
__device__ __align__(16) float g_po[(size_t)2 * HB * S * E];
__device__ float g_pm[(size_t)2 * HB * S];
__device__ float g_pl[(size_t)2 * HB * S];

// ======================= helpers =======================
__device__ __forceinline__ uint32_t smem_u32(const void* p) {
    uint32_t a;
    asm("{ .reg .u64 t; cvta.to.shared.u64 t, %1; cvt.u32.u64 %0, t; }" : "=r"(a) : "l"(p));
    return a;
}
// swizzled offset within a tile of 128-byte rows: row r, 16B-chunk c16 (0..7)
__device__ __forceinline__ uint32_t sw_off(uint32_t r, uint32_t c16) {
    return (r << 7) + (((c16 ^ r) & 7u) << 4);
}
__device__ __forceinline__ void ldsm4(uint32_t* r, uint32_t a) {
    asm volatile("ldmatrix.sync.aligned.m8n8.x4.shared.b16 {%0,%1,%2,%3}, [%4];"
        : "=r"(r[0]), "=r"(r[1]), "=r"(r[2]), "=r"(r[3]) : "r"(a));
}
__device__ __forceinline__ void ldsm4t(uint32_t* r, uint32_t a) {
    asm volatile("ldmatrix.sync.aligned.m8n8.x4.trans.shared.b16 {%0,%1,%2,%3}, [%4];"
        : "=r"(r[0]), "=r"(r[1]), "=r"(r[2]), "=r"(r[3]) : "r"(a));
}
__device__ __forceinline__ void mma16816(float* c, const uint32_t* a, uint32_t b0, uint32_t b1) {
    asm volatile("mma.sync.aligned.m16n8k16.row.col.f32.f16.f16.f32 "
        "{%0,%1,%2,%3}, {%4,%5,%6,%7}, {%8,%9}, {%0,%1,%2,%3};"
        : "+f"(c[0]), "+f"(c[1]), "+f"(c[2]), "+f"(c[3])
        : "r"(a[0]), "r"(a[1]), "r"(a[2]), "r"(a[3]), "r"(b0), "r"(b1));
}
__device__ __forceinline__ void split2(float x, float y, uint32_t& hi, uint32_t& lo) {
    __half2 h = __floats2half2_rn(x, y);
    float hx = __low2float(h), hy = __high2float(h);
    __half2 l = __floats2half2_rn(x - hx, y - hy);
    hi = *(uint32_t*)&h; lo = *(uint32_t*)&l;
}
#define CP_COMMIT()  asm volatile("cp.async.commit_group;" ::: "memory")
#define CP_WAIT1()   asm volatile("cp.async.wait_group 1;" ::: "memory")
#define CP_WAIT0()   asm volatile("cp.async.wait_group 0;" ::: "memory")

// cp.async a tile of R rows x 64 fp16 (128B/row) into swizzled smem (256 threads)
template<int R>
__device__ __forceinline__ void cpa_tile(const __half* __restrict__ g, int ldg,
                                         uint32_t sdst, int t)
{
    #pragma unroll
    for (int i = 0; i < (R * 8) / 256; i++) {
        int f = i * 256 + t;
        uint32_t r = (uint32_t)(f >> 3), c = (uint32_t)(f & 7);
        asm volatile("cp.async.cg.shared.global [%0], [%1], 16;"
            :: "r"(sdst + sw_off(r, c)), "l"(g + (size_t)r * ldg + c * 8));
    }
}

// ======================= fused prep: fp32 -> fp16 hi/lo =======================
__global__ void prep_kernel(const float* __restrict__ x,
                            const float* __restrict__ Wq, const float* __restrict__ Wk,
                            const float* __restrict__ Wv, const float* __restrict__ Wo)
{
    int i = blockIdx.x * 256 + threadIdx.x;
    float v;
    __half *dh, *dl;
    if (i < XN) {
        v = x[i];
        dh = g_x_hi + i; dl = g_x_lo + i;
    } else if (i < XN + 3 * HED) {
        int i2 = i - XN;
        int w = i2 / HED, r2 = i2 % HED;
        int k = r2 % D, row = r2 / D;
        int h = row / E, e = row % E;
        const float* W = (w == 0) ? Wq : (w == 1) ? Wk : Wv;
        v = W[((size_t)h * D + k) * E + e];
        dh = g_wt_hi + i2; dl = g_wt_lo + i2;
    } else if (i < XN + 3 * HED + D * D) {
        int i3 = i - XN - 3 * HED;
        int k = i3 % D, n = i3 / D;
        v = Wo[(size_t)k * D + n];
        dh = g_wo_hi + i3; dl = g_wo_lo + i3;
    } else return;
    __half hv = __float2half_rn(v);
    *dh = hv;
    *dl = __float2half_rn(v - __half2float(hv));
}

// ======================= GEMM core: CTA 128x64, 8 warps (4x2), warp tile 32x32 ==========
struct Acc64 { float a[2][4][4]; };
#define G_STAGE 49152

__device__ __forceinline__ void gemm_core(
    const __half* __restrict__ Ah_g, const __half* __restrict__ Al_g, int lda,
    const __half* __restrict__ Bh_g, const __half* __restrict__ Bl_g, int ldb,
    uint32_t sb, int t, Acc64& C, bool use_blo)
{
    const int lane = t & 31, wid = t >> 5;
    const int wm = (wid >> 1) * 32, wn = (wid & 1) * 32;

    cpa_tile<128>(Ah_g, lda, sb, t);
    cpa_tile<128>(Al_g, lda, sb + 16384, t);
    cpa_tile<64>(Bh_g, ldb, sb + 32768, t);
    if (use_blo) cpa_tile<64>(Bl_g, ldb, sb + 40960, t);
    CP_COMMIT();

    const uint32_t a_row  = (uint32_t)(wm + (lane & 15));
    const uint32_t a_chi  = (uint32_t)((lane >> 4) & 1);
    const uint32_t b_row0 = (uint32_t)(wn + (lane & 7) + ((lane & 16) >> 1));
    const uint32_t b_chi  = (uint32_t)((lane >> 3) & 1);

    #pragma unroll 1
    for (int c = 0; c < 12; c++) {
        if (c + 1 < 12) {
            uint32_t st = sb + (uint32_t)((c + 1) & 1) * G_STAGE;
            cpa_tile<128>(Ah_g + (c + 1) * 64, lda, st, t);
            cpa_tile<128>(Al_g + (c + 1) * 64, lda, st + 16384, t);
            cpa_tile<64>(Bh_g + (c + 1) * 64, ldb, st + 32768, t);
            if (use_blo) cpa_tile<64>(Bl_g + (c + 1) * 64, ldb, st + 40960, t);
            CP_COMMIT();
            CP_WAIT1();
        } else {
            CP_WAIT0();
        }
        __syncthreads();

        const uint32_t cs = sb + (uint32_t)(c & 1) * G_STAGE;
        const uint32_t uAh = cs, uAl = cs + 16384, uBh = cs + 32768, uBl = cs + 40960;

        #pragma unroll
        for (int ks = 0; ks < 4; ks++) {
            const uint32_t c16a = (uint32_t)(ks * 2) + a_chi;
            const uint32_t c16b = (uint32_t)(ks * 2) + b_chi;
            uint32_t ah0[4], ah1[4], al0[4], al1[4];
            ldsm4(ah0, uAh + sw_off(a_row, c16a));
            ldsm4(ah1, uAh + sw_off(a_row + 16, c16a));
            ldsm4(al0, uAl + sw_off(a_row, c16a));
            ldsm4(al1, uAl + sw_off(a_row + 16, c16a));
            #pragma unroll
            for (int np = 0; np < 2; np++) {
                uint32_t bh[4];
                ldsm4(bh, uBh + sw_off(b_row0 + np * 16, c16b));
                mma16816(C.a[0][2*np],   ah0, bh[0], bh[1]);
                mma16816(C.a[0][2*np+1], ah0, bh[2], bh[3]);
                mma16816(C.a[1][2*np],   ah1, bh[0], bh[1]);
                mma16816(C.a[1][2*np+1], ah1, bh[2], bh[3]);
                mma16816(C.a[0][2*np],   al0, bh[0], bh[1]);
                mma16816(C.a[0][2*np+1], al0, bh[2], bh[3]);
                mma16816(C.a[1][2*np],   al1, bh[0], bh[1]);
                mma16816(C.a[1][2*np+1], al1, bh[2], bh[3]);
                if (use_blo) {
                    uint32_t bl[4];
                    ldsm4(bl, uBl + sw_off(b_row0 + np * 16, c16b));
                    mma16816(C.a[0][2*np],   ah0, bl[0], bl[1]);
                    mma16816(C.a[0][2*np+1], ah0, bl[2], bl[3]);
                    mma16816(C.a[1][2*np],   ah1, bl[0], bl[1]);
                    mma16816(C.a[1][2*np+1], ah1, bl[2], bl[3]);
                }
            }
        }
        __syncthreads();
    }
}

// ======================= QKV GEMM kernel: CTA 128(m) x 64(one head) =======================
__global__ __launch_bounds__(256, 2) void qkv_mma_kernel(
    const float* __restrict__ bq, const float* __restrict__ bk, const float* __restrict__ bv)
{
    extern __shared__ __align__(16) char smem[];
    const uint32_t sb = smem_u32(smem);
    const int t = threadIdx.x, lane = t & 31, wid = t >> 5;
    const int m0 = blockIdx.x * 128;
    const int zz = blockIdx.y;             // 0..35
    const int which = zz / H;
    const int h = zz % H;

    Acc64 C;
    #pragma unroll
    for (int i = 0; i < 2; i++)
        #pragma unroll
        for (int j = 0; j < 4; j++)
            C.a[i][j][0] = C.a[i][j][1] = C.a[i][j][2] = C.a[i][j][3] = 0.f;

    gemm_core(g_x_hi + (size_t)m0 * D, g_x_lo + (size_t)m0 * D, D,
              g_wt_hi + ((size_t)which * H + h) * E * D,
              g_wt_lo + ((size_t)which * H + h) * E * D, D,
              sb, t, C, which != 2);   // V: 2-product

    const float* bias = (which == 0) ? bq : (which == 1) ? bk : bv;
    const int g = lane >> 2, j2 = (lane & 3) * 2;
    const int wm = (wid >> 1) * 32, wn = (wid & 1) * 32;
    const size_t obase = ((size_t)which * H + h) * BS * E;

    #pragma unroll
    for (int mi = 0; mi < 2; mi++) {
        const int mA = m0 + wm + mi * 16 + g;
        #pragma unroll
        for (int nt = 0; nt < 4; nt++) {
            const int e = wn + nt * 8 + j2;
            const float b0f = bias[h * E + e], b1f = bias[h * E + e + 1];
            uint32_t hi, lo;
            split2(C.a[mi][nt][0] + b0f, C.a[mi][nt][1] + b1f, hi, lo);
            *(uint32_t*)(g_qkvb_hi + obase + (size_t)mA * E + e) = hi;
            *(uint32_t*)(g_qkvb_lo + obase + (size_t)mA * E + e) = lo;
            split2(C.a[mi][nt][2] + b0f, C.a[mi][nt][3] + b1f, hi, lo);
            *(uint32_t*)(g_qkvb_hi + obase + (size_t)(mA + 8) * E + e) = hi;
            *(uint32_t*)(g_qkvb_lo + obase + (size_t)(mA + 8) * E + e) = lo;
        }
    }
}

// ======================= output projection: CTA 128(m) x 64(n), 2-product ===============
__global__ __launch_bounds__(256, 2) void proj_mma_kernel(
    const float* __restrict__ bo, float* __restrict__ out)
{
    extern __shared__ __align__(16) char smem[];
    const uint32_t sb = smem_u32(smem);
    const int t = threadIdx.x, lane = t & 31, wid = t >> 5;
    const int m0 = blockIdx.x * 128;
    const int n0 = blockIdx.y * 64;

    Acc64 C;
    #pragma unroll
    for (int i = 0; i < 2; i++)
        #pragma unroll
        for (int j = 0; j < 4; j++)
            C.a[i][j][0] = C.a[i][j][1] = C.a[i][j][2] = C.a[i][j][3] = 0.f;

    gemm_core(g_att_hi + (size_t)m0 * D, g_att_lo + (size_t)m0 * D, D,
              g_wo_hi + (size_t)n0 * D, g_wo_lo + (size_t)n0 * D, D,
              sb, t, C, false);

    const int g = lane >> 2, j2 = (lane & 3) * 2;
    const int wm = (wid >> 1) * 32, wn = (wid & 1) * 32;

    #pragma unroll
    for (int mi = 0; mi < 2; mi++) {
        const int mA = m0 + wm + mi * 16 + g;
        #pragma unroll
        for (int nt = 0; nt < 4; nt++) {
            const int n = n0 + wn + nt * 8 + j2;
            const float b0f = bo[n], b1f = bo[n + 1];
            float2 v0 = { C.a[mi][nt][0] + b0f, C.a[mi][nt][1] + b1f };
            float2 v1 = { C.a[mi][nt][2] + b0f, C.a[mi][nt][3] + b1f };
            *(float2*)(out + (size_t)mA * D + n) = v0;
            *(float2*)(out + (size_t)(mA + 8) * D + n) = v1;
        }
    }
}

// ======================= flash attention, split-KV x2 =======================
// grid (S/128, HB, 2); each CTA does 1024 kv (16 chunks of 64), writes fp32 partials.
#define A_STAGE 24576
#define A_KV    32768
#define KV_HALF 1024
__global__ __launch_bounds__(256, 2) void attn_kernel(const float* __restrict__ mask_all)
{
    extern __shared__ __align__(16) char smem[];
    const uint32_t sb = smem_u32(smem);

    const int q0 = blockIdx.x * 128;
    const int hb = blockIdx.y;
    const int half = blockIdx.z;
    const int h = hb / B, b = hb % B;
    const size_t kvoff = (size_t)(half * KV_HALF) * E;

    const __half* Qh_g = g_qkvb_hi + ((size_t)0 * H + h) * BS * E + (size_t)(b * S + q0) * E;
    const __half* Ql_g = g_qkvb_lo + ((size_t)0 * H + h) * BS * E + (size_t)(b * S + q0) * E;
    const __half* Kh_g = g_qkvb_hi + ((size_t)1 * H + h) * BS * E + (size_t)b * S * E + kvoff;
    const __half* Kl_g = g_qkvb_lo + ((size_t)1 * H + h) * BS * E + (size_t)b * S * E + kvoff;
    const __half* Vh_g = g_qkvb_hi + ((size_t)2 * H + h) * BS * E + (size_t)b * S * E + kvoff;
    const float* mask = mask_all + (size_t)(h * B + b) * S * S + half * KV_HALF;

    const int t = threadIdx.x, lane = t & 31, wid = t >> 5;
    const int g = lane >> 2, j2 = (lane & 3) * 2;
    const int r0 = wid * 16;

    // Q -> resident smem region
    cpa_tile<128>(Qh_g, E, sb, t);
    cpa_tile<128>(Ql_g, E, sb + 16384, t);
    CP_COMMIT();
    // kv chunk 0 -> stage 0
    cpa_tile<64>(Kh_g, E, sb + A_KV, t);
    cpa_tile<64>(Kl_g, E, sb + A_KV + 8192, t);
    cpa_tile<64>(Vh_g, E, sb + A_KV + 16384, t);
    CP_COMMIT();

    float m_a = -INFINITY, m_b = -INFINITY, l_a = 0.f, l_b = 0.f;
    float o[8][4];
    #pragma unroll
    for (int et = 0; et < 8; et++)
        o[et][0] = o[et][1] = o[et][2] = o[et][3] = 0.f;

    const uint32_t a_row  = (uint32_t)(r0 + (lane & 15));
    const uint32_t a_chi  = (uint32_t)((lane >> 4) & 1);
    const uint32_t b_row0 = (uint32_t)((lane & 7) + ((lane & 16) >> 1));
    const uint32_t b_chi  = (uint32_t)((lane >> 3) & 1);
    const uint32_t v_row  = (uint32_t)(lane & 15);
    const uint32_t v_chi  = (uint32_t)((lane >> 4) & 1);

    #pragma unroll 1
    for (int jc = 0; jc < 16; jc++) {
        const int j0 = jc * 64;

        // mask loads initialize S accumulators; overlap pipeline wait
        float s[8][4];
        const float* mra = mask + (size_t)(q0 + r0 + g) * S + j0 + j2;
        const float* mrb = mra + 8 * S;
        #pragma unroll
        for (int nt = 0; nt < 8; nt++) {
            float2 ma = *(const float2*)(mra + nt * 8);
            float2 mb = *(const float2*)(mrb + nt * 8);
            s[nt][0] = ma.x; s[nt][1] = ma.y; s[nt][2] = mb.x; s[nt][3] = mb.y;
        }

        if (jc + 1 < 16) {
            const uint32_t ns = sb + A_KV + (uint32_t)((jc + 1) & 1) * A_STAGE;
            const size_t go = (size_t)(j0 + 64) * E;
            cpa_tile<64>(Kh_g + go, E, ns, t);
            cpa_tile<64>(Kl_g + go, E, ns + 8192, t);
            cpa_tile<64>(Vh_g + go, E, ns + 16384, t);
            CP_COMMIT();
            CP_WAIT1();
        } else {
            CP_WAIT0();
        }
        __syncthreads();

        const uint32_t cs = sb + A_KV + (uint32_t)(jc & 1) * A_STAGE;
        const uint32_t uKh = cs, uKl = cs + 8192, uVh = cs + 16384;

        // ---- S += Q K^T (3-product) ----
        #pragma unroll
        for (int ks = 0; ks < 4; ks++) {
            const uint32_t c16a = (uint32_t)(ks * 2) + a_chi;
            const uint32_t c16b = (uint32_t)(ks * 2) + b_chi;
            uint32_t qh[4], ql[4];
            ldsm4(qh, sb + sw_off(a_row, c16a));
            ldsm4(ql, sb + 16384 + sw_off(a_row, c16a));
            #pragma unroll
            for (int np = 0; np < 4; np++) {
                uint32_t bh[4], bl[4];
                const uint32_t bo_ = sw_off(b_row0 + np * 16, c16b);
                ldsm4(bh, uKh + bo_);
                ldsm4(bl, uKl + bo_);
                mma16816(s[2*np],   qh, bh[0], bh[1]);
                mma16816(s[2*np+1], qh, bh[2], bh[3]);
                mma16816(s[2*np],   qh, bl[0], bl[1]);
                mma16816(s[2*np+1], qh, bl[2], bl[3]);
                mma16816(s[2*np],   ql, bh[0], bh[1]);
                mma16816(s[2*np+1], ql, bh[2], bh[3]);
            }
        }

        // ---- online softmax (rows g and g+8) ----
        float mxa = -INFINITY, mxb = -INFINITY;
        #pragma unroll
        for (int nt = 0; nt < 8; nt++) {
            mxa = fmaxf(mxa, fmaxf(s[nt][0], s[nt][1]));
            mxb = fmaxf(mxb, fmaxf(s[nt][2], s[nt][3]));
        }
        mxa = fmaxf(mxa, __shfl_xor_sync(0xffffffffu, mxa, 1));
        mxa = fmaxf(mxa, __shfl_xor_sync(0xffffffffu, mxa, 2));
        mxb = fmaxf(mxb, __shfl_xor_sync(0xffffffffu, mxb, 1));
        mxb = fmaxf(mxb, __shfl_xor_sync(0xffffffffu, mxb, 2));

        const float mna = fmaxf(m_a, mxa), mnb = fmaxf(m_b, mxb);
        const float aa = __expf(m_a - mna), ab = __expf(m_b - mnb);
        float sa = 0.f, sb2 = 0.f;
        #pragma unroll
        for (int nt = 0; nt < 8; nt++) {
            s[nt][0] = __expf(s[nt][0] - mna); sa += s[nt][0];
            s[nt][1] = __expf(s[nt][1] - mna); sa += s[nt][1];
            s[nt][2] = __expf(s[nt][2] - mnb); sb2 += s[nt][2];
            s[nt][3] = __expf(s[nt][3] - mnb); sb2 += s[nt][3];
        }
        sa  += __shfl_xor_sync(0xffffffffu, sa, 1);
        sa  += __shfl_xor_sync(0xffffffffu, sa, 2);
        sb2 += __shfl_xor_sync(0xffffffffu, sb2, 1);
        sb2 += __shfl_xor_sync(0xffffffffu, sb2, 2);
        l_a = l_a * aa + sa; l_b = l_b * ab + sb2;
        m_a = mna; m_b = mnb;
        #pragma unroll
        for (int et = 0; et < 8; et++) {
            o[et][0] *= aa; o[et][1] *= aa;
            o[et][2] *= ab; o[et][3] *= ab;
        }

        // ---- O += P V (P split hi/lo in regs; 2-product) ----
        #pragma unroll
        for (int ks2 = 0; ks2 < 4; ks2++) {
            const int nt0 = 2 * ks2, nt1 = nt0 + 1;
            uint32_t a_hi[4], a_lo[4];
            split2(s[nt0][0], s[nt0][1], a_hi[0], a_lo[0]);
            split2(s[nt0][2], s[nt0][3], a_hi[1], a_lo[1]);
            split2(s[nt1][0], s[nt1][1], a_hi[2], a_lo[2]);
            split2(s[nt1][2], s[nt1][3], a_hi[3], a_lo[3]);
            #pragma unroll
            for (int ep = 0; ep < 4; ep++) {
                uint32_t vh[4];
                ldsm4t(vh, uVh + sw_off(v_row + ks2 * 16, (uint32_t)(ep * 2) + v_chi));
                mma16816(o[2*ep],   a_hi, vh[0], vh[1]);
                mma16816(o[2*ep+1], a_hi, vh[2], vh[3]);
                mma16816(o[2*ep],   a_lo, vh[0], vh[1]);
                mma16816(o[2*ep+1], a_lo, vh[2], vh[3]);
            }
        }
        __syncthreads();
    }

    // ---- epilogue: write fp32 partials (unnormalized O, m, l) ----
    const int rowA = q0 + r0 + g, rowB = rowA + 8;
    const size_t baseA = ((size_t)(half * HB + hb) * S + rowA) * E;
    const size_t baseB = ((size_t)(half * HB + hb) * S + rowB) * E;
    #pragma unroll
    for (int et = 0; et < 8; et++) {
        float2 va = { o[et][0], o[et][1] };
        float2 vb = { o[et][2], o[et][3] };
        *(float2*)(g_po + baseA + et * 8 + j2) = va;
        *(float2*)(g_po + baseB + et * 8 + j2) = vb;
    }
    if ((lane & 3) == 0) {
        g_pm[(size_t)(half * HB + hb) * S + rowA] = m_a;
        g_pl[(size_t)(half * HB + hb) * S + rowA] = l_a;
        g_pm[(size_t)(half * HB + hb) * S + rowB] = m_b;
        g_pl[(size_t)(half * HB + hb) * S + rowB] = l_b;
    }
}

// ======================= combine: merge kv halves, emit hi/lo att =======================
// one warp per (hb, row); lane handles 2 columns
__global__ __launch_bounds__(256) void combine_kernel()
{
    const int gw = blockIdx.x * 8 + (threadIdx.x >> 5);   // 0 .. HB*S-1
    const int lane = threadIdx.x & 31;
    const int hb = gw >> 11;          // /2048
    const int row = gw & 2047;
    const int h = hb / B, b = hb % B;

    const size_t r1 = (size_t)hb * S + row;
    const size_t r2 = (size_t)(HB + hb) * S + row;
    const float m1 = g_pm[r1], m2 = g_pm[r2];
    const float l1 = g_pl[r1], l2 = g_pl[r2];
    const float m = fmaxf(m1, m2);
    float w1 = __expf(m1 - m), w2 = __expf(m2 - m);
    const float inv = 1.f / (l1 * w1 + l2 * w2);
    w1 *= inv; w2 *= inv;

    float2 o1 = *(const float2*)(g_po + r1 * E + lane * 2);
    float2 o2 = *(const float2*)(g_po + r2 * E + lane * 2);
    const float x = o1.x * w1 + o2.x * w2;
    const float y = o1.y * w1 + o2.y * w2;
    uint32_t hi, lo;
    split2(x, y, hi, lo);
    const size_t dst = (size_t)(b * S + row) * D + h * E + lane * 2;
    *(uint32_t*)(g_att_hi + dst) = hi;
    *(uint32_t*)(g_att_lo + dst) = lo;
}

// ======================= Launch =======================
extern "C" void kernel_launch(void* const* d_in, const int* in_sizes, int n_in,
                              void* d_out, int out_size)
{
    const float* x    = (const float*)d_in[0];
    const float* mask = (const float*)d_in[1];
    const float* Wq   = (const float*)d_in[2];
    const float* bq   = (const float*)d_in[3];
    const float* Wk   = (const float*)d_in[4];
    const float* bk   = (const float*)d_in[5];
    const float* Wv   = (const float*)d_in[6];
    const float* bv   = (const float*)d_in[7];
    const float* Wo   = (const float*)d_in[8];
    const float* bo   = (const float*)d_in[9];

    const int smem_gemm = 2 * G_STAGE;          // 98,304 B
    const int smem_attn = A_KV + 2 * A_STAGE;   // 81,920 B
    cudaFuncSetAttribute(qkv_mma_kernel,  cudaFuncAttributeMaxDynamicSharedMemorySize, smem_gemm);
    cudaFuncSetAttribute(proj_mma_kernel, cudaFuncAttributeMaxDynamicSharedMemorySize, smem_gemm);
    cudaFuncSetAttribute(attn_kernel,     cudaFuncAttributeMaxDynamicSharedMemorySize, smem_attn);

    const int prep_n = XN + 3 * HED + D * D;
    prep_kernel<<< (prep_n + 255) / 256, 256 >>>(x, Wq, Wk, Wv, Wo);

    qkv_mma_kernel <<< dim3(BS / 128, 3 * H), 256, smem_gemm >>>(bq, bk, bv);
    attn_kernel    <<< dim3(S / 128, HB, 2), 256, smem_attn >>>(mask);
    combine_kernel <<< (HB * S) / 8, 256 >>>();
    proj_mma_kernel<<< dim3(BS / 128, D / 64), 256, smem_gemm >>>(bo, (float*)d_out);
}

// round 9
// speedup vs baseline: 1.0861x; 1.0861x over previous
#include <cuda_runtime.h>
#include <cuda_fp16.h>
#include <math.h>
#include <stdint.h>

#define B 2
#define S 2048
#define D 768
#define H 12
#define E 64
#define BS (B*S)   // 4096
#define XN (BS*D)
#define HED (H*E*D)

// ---- scratch (static device globals; no runtime allocation) ----
__device__ __align__(16) __half g_x_hi[(size_t)BS * D];
__device__ __align__(16) __half g_x_lo[(size_t)BS * D];
__device__ __align__(16) __half g_wt_hi[(size_t)3 * H * E * D]; // [which][h*E+e][k]
__device__ __align__(16) __half g_wt_lo[(size_t)3 * H * E * D];
__device__ __align__(16) __half g_wo_hi[(size_t)D * D];         // [n][k]
__device__ __align__(16) __half g_wo_lo[(size_t)D * D];
__device__ __align__(16) __half g_qkvb_hi[(size_t)3 * H * BS * E]; // [which][h][b*S+s][e]
__device__ __align__(16) __half g_qkvb_lo[(size_t)3 * H * BS * E];
__device__ __align__(16) __half g_att_hi[(size_t)BS * D];       // [b*S+s][h*E+e]
__device__ __align__(16) __half g_att_lo[(size_t)BS * D];

// ======================= helpers =======================
__device__ __forceinline__ uint32_t smem_u32(const void* p) {
    uint32_t a;
    asm("{ .reg .u64 t; cvta.to.shared.u64 t, %1; cvt.u32.u64 %0, t; }" : "=r"(a) : "l"(p));
    return a;
}
// swizzled offset within a tile of 128-byte rows: row r, 16B-chunk c16 (0..7)
__device__ __forceinline__ uint32_t sw_off(uint32_t r, uint32_t c16) {
    return (r << 7) + (((c16 ^ r) & 7u) << 4);
}
__device__ __forceinline__ void ldsm4(uint32_t* r, uint32_t a) {
    asm volatile("ldmatrix.sync.aligned.m8n8.x4.shared.b16 {%0,%1,%2,%3}, [%4];"
        : "=r"(r[0]), "=r"(r[1]), "=r"(r[2]), "=r"(r[3]) : "r"(a));
}
__device__ __forceinline__ void ldsm4t(uint32_t* r, uint32_t a) {
    asm volatile("ldmatrix.sync.aligned.m8n8.x4.trans.shared.b16 {%0,%1,%2,%3}, [%4];"
        : "=r"(r[0]), "=r"(r[1]), "=r"(r[2]), "=r"(r[3]) : "r"(a));
}
__device__ __forceinline__ void mma16816(float* c, const uint32_t* a, uint32_t b0, uint32_t b1) {
    asm volatile("mma.sync.aligned.m16n8k16.row.col.f32.f16.f16.f32 "
        "{%0,%1,%2,%3}, {%4,%5,%6,%7}, {%8,%9}, {%0,%1,%2,%3};"
        : "+f"(c[0]), "+f"(c[1]), "+f"(c[2]), "+f"(c[3])
        : "r"(a[0]), "r"(a[1]), "r"(a[2]), "r"(a[3]), "r"(b0), "r"(b1));
}
__device__ __forceinline__ void split2(float x, float y, uint32_t& hi, uint32_t& lo) {
    __half2 h = __floats2half2_rn(x, y);
    float hx = __low2float(h), hy = __high2float(h);
    __half2 l = __floats2half2_rn(x - hx, y - hy);
    hi = *(uint32_t*)&h; lo = *(uint32_t*)&l;
}
__device__ __forceinline__ uint32_t pack2(float x, float y) {
    __half2 h = __floats2half2_rn(x, y);
    return *(uint32_t*)&h;
}
#define CP_COMMIT()  asm volatile("cp.async.commit_group;" ::: "memory")
#define CP_WAIT1()   asm volatile("cp.async.wait_group 1;" ::: "memory")
#define CP_WAIT0()   asm volatile("cp.async.wait_group 0;" ::: "memory")

// cp.async a tile of R rows x 64 fp16 (128B/row) into swizzled smem (256 threads)
template<int R>
__device__ __forceinline__ void cpa_tile(const __half* __restrict__ g, int ldg,
                                         uint32_t sdst, int t)
{
    #pragma unroll
    for (int i = 0; i < (R * 8) / 256; i++) {
        int f = i * 256 + t;
        uint32_t r = (uint32_t)(f >> 3), c = (uint32_t)(f & 7);
        asm volatile("cp.async.cg.shared.global [%0], [%1], 16;"
            :: "r"(sdst + sw_off(r, c)), "l"(g + (size_t)r * ldg + c * 8));
    }
}

// ======================= fused prep: fp32 -> fp16 hi/lo =======================
__global__ void prep_kernel(const float* __restrict__ x,
                            const float* __restrict__ Wq, const float* __restrict__ Wk,
                            const float* __restrict__ Wv, const float* __restrict__ Wo)
{
    int i = blockIdx.x * 256 + threadIdx.x;
    float v;
    __half *dh, *dl;
    if (i < XN) {
        v = x[i];
        dh = g_x_hi + i; dl = g_x_lo + i;
    } else if (i < XN + 3 * HED) {
        int i2 = i - XN;
        int w = i2 / HED, r2 = i2 % HED;
        int k = r2 % D, row = r2 / D;
        int h = row / E, e = row % E;
        const float* W = (w == 0) ? Wq : (w == 1) ? Wk : Wv;
        v = W[((size_t)h * D + k) * E + e];
        dh = g_wt_hi + i2; dl = g_wt_lo + i2;
    } else if (i < XN + 3 * HED + D * D) {
        int i3 = i - XN - 3 * HED;
        int k = i3 % D, n = i3 / D;
        v = Wo[(size_t)k * D + n];
        dh = g_wo_hi + i3; dl = g_wo_lo + i3;
    } else return;
    __half hv = __float2half_rn(v);
    *dh = hv;
    *dl = __float2half_rn(v - __half2float(hv));
}

// ======================= GEMM core: CTA 128x64, 8 warps (4x2), warp tile 32x32 ==========
struct Acc64 { float a[2][4][4]; };
#define G_STAGE 49152

__device__ __forceinline__ void gemm_core(
    const __half* __restrict__ Ah_g, const __half* __restrict__ Al_g, int lda,
    const __half* __restrict__ Bh_g, const __half* __restrict__ Bl_g, int ldb,
    uint32_t sb, int t, Acc64& C, bool use_blo)
{
    const int lane = t & 31, wid = t >> 5;
    const int wm = (wid >> 1) * 32, wn = (wid & 1) * 32;

    cpa_tile<128>(Ah_g, lda, sb, t);
    cpa_tile<128>(Al_g, lda, sb + 16384, t);
    cpa_tile<64>(Bh_g, ldb, sb + 32768, t);
    if (use_blo) cpa_tile<64>(Bl_g, ldb, sb + 40960, t);
    CP_COMMIT();

    const uint32_t a_row  = (uint32_t)(wm + (lane & 15));
    const uint32_t a_chi  = (uint32_t)((lane >> 4) & 1);
    const uint32_t b_row0 = (uint32_t)(wn + (lane & 7) + ((lane & 16) >> 1));
    const uint32_t b_chi  = (uint32_t)((lane >> 3) & 1);

    #pragma unroll 1
    for (int c = 0; c < 12; c++) {
        if (c + 1 < 12) {
            uint32_t st = sb + (uint32_t)((c + 1) & 1) * G_STAGE;
            cpa_tile<128>(Ah_g + (c + 1) * 64, lda, st, t);
            cpa_tile<128>(Al_g + (c + 1) * 64, lda, st + 16384, t);
            cpa_tile<64>(Bh_g + (c + 1) * 64, ldb, st + 32768, t);
            if (use_blo) cpa_tile<64>(Bl_g + (c + 1) * 64, ldb, st + 40960, t);
            CP_COMMIT();
            CP_WAIT1();
        } else {
            CP_WAIT0();
        }
        __syncthreads();

        const uint32_t cs = sb + (uint32_t)(c & 1) * G_STAGE;
        const uint32_t uAh = cs, uAl = cs + 16384, uBh = cs + 32768, uBl = cs + 40960;

        #pragma unroll
        for (int ks = 0; ks < 4; ks++) {
            const uint32_t c16a = (uint32_t)(ks * 2) + a_chi;
            const uint32_t c16b = (uint32_t)(ks * 2) + b_chi;
            uint32_t ah0[4], ah1[4], al0[4], al1[4];
            ldsm4(ah0, uAh + sw_off(a_row, c16a));
            ldsm4(ah1, uAh + sw_off(a_row + 16, c16a));
            ldsm4(al0, uAl + sw_off(a_row, c16a));
            ldsm4(al1, uAl + sw_off(a_row + 16, c16a));
            #pragma unroll
            for (int np = 0; np < 2; np++) {
                uint32_t bh[4];
                ldsm4(bh, uBh + sw_off(b_row0 + np * 16, c16b));
                mma16816(C.a[0][2*np],   ah0, bh[0], bh[1]);
                mma16816(C.a[0][2*np+1], ah0, bh[2], bh[3]);
                mma16816(C.a[1][2*np],   ah1, bh[0], bh[1]);
                mma16816(C.a[1][2*np+1], ah1, bh[2], bh[3]);
                mma16816(C.a[0][2*np],   al0, bh[0], bh[1]);
                mma16816(C.a[0][2*np+1], al0, bh[2], bh[3]);
                mma16816(C.a[1][2*np],   al1, bh[0], bh[1]);
                mma16816(C.a[1][2*np+1], al1, bh[2], bh[3]);
                if (use_blo) {
                    uint32_t bl[4];
                    ldsm4(bl, uBl + sw_off(b_row0 + np * 16, c16b));
                    mma16816(C.a[0][2*np],   ah0, bl[0], bl[1]);
                    mma16816(C.a[0][2*np+1], ah0, bl[2], bl[3]);
                    mma16816(C.a[1][2*np],   ah1, bl[0], bl[1]);
                    mma16816(C.a[1][2*np+1], ah1, bl[2], bl[3]);
                }
            }
        }
        __syncthreads();
    }
}

// ======================= QKV GEMM kernel: CTA 128(m) x 64(one head) =======================
__global__ __launch_bounds__(256, 2) void qkv_mma_kernel(
    const float* __restrict__ bq, const float* __restrict__ bk, const float* __restrict__ bv)
{
    extern __shared__ __align__(16) char smem[];
    const uint32_t sb = smem_u32(smem);
    const int t = threadIdx.x, lane = t & 31, wid = t >> 5;
    const int m0 = blockIdx.x * 128;
    const int zz = blockIdx.y;             // 0..35
    const int which = zz / H;
    const int h = zz % H;

    Acc64 C;
    #pragma unroll
    for (int i = 0; i < 2; i++)
        #pragma unroll
        for (int j = 0; j < 4; j++)
            C.a[i][j][0] = C.a[i][j][1] = C.a[i][j][2] = C.a[i][j][3] = 0.f;

    gemm_core(g_x_hi + (size_t)m0 * D, g_x_lo + (size_t)m0 * D, D,
              g_wt_hi + ((size_t)which * H + h) * E * D,
              g_wt_lo + ((size_t)which * H + h) * E * D, D,
              sb, t, C, which != 2);   // V: 2-product

    const float* bias = (which == 0) ? bq : (which == 1) ? bk : bv;
    const int g = lane >> 2, j2 = (lane & 3) * 2;
    const int wm = (wid >> 1) * 32, wn = (wid & 1) * 32;
    const size_t obase = ((size_t)which * H + h) * BS * E;
    const bool need_lo = (which != 2);   // V-lo is never consumed (PV is 1-product)

    #pragma unroll
    for (int mi = 0; mi < 2; mi++) {
        const int mA = m0 + wm + mi * 16 + g;
        #pragma unroll
        for (int nt = 0; nt < 4; nt++) {
            const int e = wn + nt * 8 + j2;
            const float b0f = bias[h * E + e], b1f = bias[h * E + e + 1];
            uint32_t hi, lo;
            split2(C.a[mi][nt][0] + b0f, C.a[mi][nt][1] + b1f, hi, lo);
            *(uint32_t*)(g_qkvb_hi + obase + (size_t)mA * E + e) = hi;
            if (need_lo) *(uint32_t*)(g_qkvb_lo + obase + (size_t)mA * E + e) = lo;
            split2(C.a[mi][nt][2] + b0f, C.a[mi][nt][3] + b1f, hi, lo);
            *(uint32_t*)(g_qkvb_hi + obase + (size_t)(mA + 8) * E + e) = hi;
            if (need_lo) *(uint32_t*)(g_qkvb_lo + obase + (size_t)(mA + 8) * E + e) = lo;
        }
    }
}

// ======================= output projection: CTA 128(m) x 64(n), 2-product ===============
__global__ __launch_bounds__(256, 2) void proj_mma_kernel(
    const float* __restrict__ bo, float* __restrict__ out)
{
    extern __shared__ __align__(16) char smem[];
    const uint32_t sb = smem_u32(smem);
    const int t = threadIdx.x, lane = t & 31, wid = t >> 5;
    const int m0 = blockIdx.x * 128;
    const int n0 = blockIdx.y * 64;

    Acc64 C;
    #pragma unroll
    for (int i = 0; i < 2; i++)
        #pragma unroll
        for (int j = 0; j < 4; j++)
            C.a[i][j][0] = C.a[i][j][1] = C.a[i][j][2] = C.a[i][j][3] = 0.f;

    gemm_core(g_att_hi + (size_t)m0 * D, g_att_lo + (size_t)m0 * D, D,
              g_wo_hi + (size_t)n0 * D, g_wo_lo + (size_t)n0 * D, D,
              sb, t, C, false);

    const int g = lane >> 2, j2 = (lane & 3) * 2;
    const int wm = (wid >> 1) * 32, wn = (wid & 1) * 32;

    #pragma unroll
    for (int mi = 0; mi < 2; mi++) {
        const int mA = m0 + wm + mi * 16 + g;
        #pragma unroll
        for (int nt = 0; nt < 4; nt++) {
            const int n = n0 + wn + nt * 8 + j2;
            const float b0f = bo[n], b1f = bo[n + 1];
            float2 v0 = { C.a[mi][nt][0] + b0f, C.a[mi][nt][1] + b1f };
            float2 v1 = { C.a[mi][nt][2] + b0f, C.a[mi][nt][3] + b1f };
            *(float2*)(out + (size_t)mA * D + n) = v0;
            *(float2*)(out + (size_t)(mA + 8) * D + n) = v1;
        }
    }
}

// ======================= flash attention =======================
// 256 threads, 8 warps x 16 q-rows = 128-row q tile; kv chunks of 64, 32 chunks.
// S = QK^T: 3-product.  PV: 1-product (P as plain fp16).
#define A_STAGE 24576
#define A_KV    32768
__global__ __launch_bounds__(256, 2) void attn_kernel(const float* __restrict__ mask_all)
{
    extern __shared__ __align__(16) char smem[];
    const uint32_t sb = smem_u32(smem);

    const int q0 = blockIdx.x * 128;
    const int hb = blockIdx.y;
    const int h = hb / B, b = hb % B;

    const __half* Qh_g = g_qkvb_hi + ((size_t)0 * H + h) * BS * E + (size_t)(b * S + q0) * E;
    const __half* Ql_g = g_qkvb_lo + ((size_t)0 * H + h) * BS * E + (size_t)(b * S + q0) * E;
    const __half* Kh_g = g_qkvb_hi + ((size_t)1 * H + h) * BS * E + (size_t)b * S * E;
    const __half* Kl_g = g_qkvb_lo + ((size_t)1 * H + h) * BS * E + (size_t)b * S * E;
    const __half* Vh_g = g_qkvb_hi + ((size_t)2 * H + h) * BS * E + (size_t)b * S * E;
    const float* mask = mask_all + (size_t)(h * B + b) * S * S;

    const int t = threadIdx.x, lane = t & 31, wid = t >> 5;
    const int g = lane >> 2, j2 = (lane & 3) * 2;
    const int r0 = wid * 16;

    // Q -> resident smem region
    cpa_tile<128>(Qh_g, E, sb, t);
    cpa_tile<128>(Ql_g, E, sb + 16384, t);
    CP_COMMIT();
    // kv chunk 0 -> stage 0
    cpa_tile<64>(Kh_g, E, sb + A_KV, t);
    cpa_tile<64>(Kl_g, E, sb + A_KV + 8192, t);
    cpa_tile<64>(Vh_g, E, sb + A_KV + 16384, t);
    CP_COMMIT();

    float m_a = -INFINITY, m_b = -INFINITY, l_a = 0.f, l_b = 0.f;
    float o[8][4];
    #pragma unroll
    for (int et = 0; et < 8; et++)
        o[et][0] = o[et][1] = o[et][2] = o[et][3] = 0.f;

    const uint32_t a_row  = (uint32_t)(r0 + (lane & 15));
    const uint32_t a_chi  = (uint32_t)((lane >> 4) & 1);
    const uint32_t b_row0 = (uint32_t)((lane & 7) + ((lane & 16) >> 1));
    const uint32_t b_chi  = (uint32_t)((lane >> 3) & 1);
    const uint32_t v_row  = (uint32_t)(lane & 15);
    const uint32_t v_chi  = (uint32_t)((lane >> 4) & 1);

    #pragma unroll 1
    for (int jc = 0; jc < 32; jc++) {
        const int j0 = jc * 64;

        // mask loads initialize S accumulators; overlap pipeline wait
        float s[8][4];
        const float* mra = mask + (size_t)(q0 + r0 + g) * S + j0 + j2;
        const float* mrb = mra + 8 * S;
        #pragma unroll
        for (int nt = 0; nt < 8; nt++) {
            float2 ma = *(const float2*)(mra + nt * 8);
            float2 mb = *(const float2*)(mrb + nt * 8);
            s[nt][0] = ma.x; s[nt][1] = ma.y; s[nt][2] = mb.x; s[nt][3] = mb.y;
        }

        if (jc + 1 < 32) {
            const uint32_t ns = sb + A_KV + (uint32_t)((jc + 1) & 1) * A_STAGE;
            const size_t go = (size_t)(j0 + 64) * E;
            cpa_tile<64>(Kh_g + go, E, ns, t);
            cpa_tile<64>(Kl_g + go, E, ns + 8192, t);
            cpa_tile<64>(Vh_g + go, E, ns + 16384, t);
            CP_COMMIT();
            CP_WAIT1();
        } else {
            CP_WAIT0();
        }
        __syncthreads();

        const uint32_t cs = sb + A_KV + (uint32_t)(jc & 1) * A_STAGE;
        const uint32_t uKh = cs, uKl = cs + 8192, uVh = cs + 16384;

        // ---- S += Q K^T (3-product) ----
        #pragma unroll
        for (int ks = 0; ks < 4; ks++) {
            const uint32_t c16a = (uint32_t)(ks * 2) + a_chi;
            const uint32_t c16b = (uint32_t)(ks * 2) + b_chi;
            uint32_t qh[4], ql[4];
            ldsm4(qh, sb + sw_off(a_row, c16a));
            ldsm4(ql, sb + 16384 + sw_off(a_row, c16a));
            #pragma unroll
            for (int np = 0; np < 4; np++) {
                uint32_t bh[4], bl[4];
                const uint32_t bo_ = sw_off(b_row0 + np * 16, c16b);
                ldsm4(bh, uKh + bo_);
                ldsm4(bl, uKl + bo_);
                mma16816(s[2*np],   qh, bh[0], bh[1]);
                mma16816(s[2*np+1], qh, bh[2], bh[3]);
                mma16816(s[2*np],   qh, bl[0], bl[1]);
                mma16816(s[2*np+1], qh, bl[2], bl[3]);
                mma16816(s[2*np],   ql, bh[0], bh[1]);
                mma16816(s[2*np+1], ql, bh[2], bh[3]);
            }
        }

        // ---- online softmax (rows g and g+8) ----
        float mxa = -INFINITY, mxb = -INFINITY;
        #pragma unroll
        for (int nt = 0; nt < 8; nt++) {
            mxa = fmaxf(mxa, fmaxf(s[nt][0], s[nt][1]));
            mxb = fmaxf(mxb, fmaxf(s[nt][2], s[nt][3]));
        }
        mxa = fmaxf(mxa, __shfl_xor_sync(0xffffffffu, mxa, 1));
        mxa = fmaxf(mxa, __shfl_xor_sync(0xffffffffu, mxa, 2));
        mxb = fmaxf(mxb, __shfl_xor_sync(0xffffffffu, mxb, 1));
        mxb = fmaxf(mxb, __shfl_xor_sync(0xffffffffu, mxb, 2));

        const float mna = fmaxf(m_a, mxa), mnb = fmaxf(m_b, mxb);
        const float aa = __expf(m_a - mna), ab = __expf(m_b - mnb);
        float sa = 0.f, sb2 = 0.f;
        #pragma unroll
        for (int nt = 0; nt < 8; nt++) {
            s[nt][0] = __expf(s[nt][0] - mna); sa += s[nt][0];
            s[nt][1] = __expf(s[nt][1] - mna); sa += s[nt][1];
            s[nt][2] = __expf(s[nt][2] - mnb); sb2 += s[nt][2];
            s[nt][3] = __expf(s[nt][3] - mnb); sb2 += s[nt][3];
        }
        sa  += __shfl_xor_sync(0xffffffffu, sa, 1);
        sa  += __shfl_xor_sync(0xffffffffu, sa, 2);
        sb2 += __shfl_xor_sync(0xffffffffu, sb2, 1);
        sb2 += __shfl_xor_sync(0xffffffffu, sb2, 2);
        l_a = l_a * aa + sa; l_b = l_b * ab + sb2;
        m_a = mna; m_b = mnb;
        #pragma unroll
        for (int et = 0; et < 8; et++) {
            o[et][0] *= aa; o[et][1] *= aa;
            o[et][2] *= ab; o[et][3] *= ab;
        }

        // ---- O += P V (P plain fp16: 1-product) ----
        #pragma unroll
        for (int ks2 = 0; ks2 < 4; ks2++) {
            const int nt0 = 2 * ks2, nt1 = nt0 + 1;
            uint32_t a_p[4];
            a_p[0] = pack2(s[nt0][0], s[nt0][1]);
            a_p[1] = pack2(s[nt0][2], s[nt0][3]);
            a_p[2] = pack2(s[nt1][0], s[nt1][1]);
            a_p[3] = pack2(s[nt1][2], s[nt1][3]);
            #pragma unroll
            for (int ep = 0; ep < 4; ep++) {
                uint32_t vh[4];
                ldsm4t(vh, uVh + sw_off(v_row + ks2 * 16, (uint32_t)(ep * 2) + v_chi));
                mma16816(o[2*ep],   a_p, vh[0], vh[1]);
                mma16816(o[2*ep+1], a_p, vh[2], vh[3]);
            }
        }
        __syncthreads();
    }

    // ---- epilogue: normalize, split hi/lo, concat-head layout ----
    const float ia = 1.f / l_a, ib = 1.f / l_b;
    const int rowA = q0 + r0 + g, rowB = rowA + 8;
    #pragma unroll
    for (int et = 0; et < 8; et++) {
        const size_t col = (size_t)h * E + et * 8 + j2;
        uint32_t hi, lo;
        split2(o[et][0] * ia, o[et][1] * ia, hi, lo);
        *(uint32_t*)(g_att_hi + (size_t)(b * S + rowA) * D + col) = hi;
        *(uint32_t*)(g_att_lo + (size_t)(b * S + rowA) * D + col) = lo;
        split2(o[et][2] * ib, o[et][3] * ib, hi, lo);
        *(uint32_t*)(g_att_hi + (size_t)(b * S + rowB) * D + col) = hi;
        *(uint32_t*)(g_att_lo + (size_t)(b * S + rowB) * D + col) = lo;
    }
}

// ======================= Launch =======================
extern "C" void kernel_launch(void* const* d_in, const int* in_sizes, int n_in,
                              void* d_out, int out_size)
{
    const float* x    = (const float*)d_in[0];
    const float* mask = (const float*)d_in[1];
    const float* Wq   = (const float*)d_in[2];
    const float* bq   = (const float*)d_in[3];
    const float* Wk   = (const float*)d_in[4];
    const float* bk   = (const float*)d_in[5];
    const float* Wv   = (const float*)d_in[6];
    const float* bv   = (const float*)d_in[7];
    const float* Wo   = (const float*)d_in[8];
    const float* bo   = (const float*)d_in[9];

    const int smem_gemm = 2 * G_STAGE;          // 98,304 B
    const int smem_attn = A_KV + 2 * A_STAGE;   // 81,920 B
    cudaFuncSetAttribute(qkv_mma_kernel,  cudaFuncAttributeMaxDynamicSharedMemorySize, smem_gemm);
    cudaFuncSetAttribute(proj_mma_kernel, cudaFuncAttributeMaxDynamicSharedMemorySize, smem_gemm);
    cudaFuncSetAttribute(attn_kernel,     cudaFuncAttributeMaxDynamicSharedMemorySize, smem_attn);

    const int prep_n = XN + 3 * HED + D * D;
    prep_kernel<<< (prep_n + 255) / 256, 256 >>>(x, Wq, Wk, Wv, Wo);

    qkv_mma_kernel <<< dim3(BS / 128, 3 * H), 256, smem_gemm >>>(bq, bk, bv);
    attn_kernel    <<< dim3(S / 128, H * B), 256, smem_attn >>>(mask);
    proj_mma_kernel<<< dim3(BS / 128, D / 64), 256, smem_gemm >>>(bo, (float*)d_out);
}

// round 10
// speedup vs baseline: 1.2519x; 1.1527x over previous
#include <cuda_runtime.h>
#include <cuda_fp16.h>
#include <math.h>
#include <stdint.h>

#define B 2
#define S 2048
#define D 768
#define H 12
#define E 64
#define BS (B*S)   // 4096
#define XN (BS*D)
#define HED (H*E*D)

// ---- scratch (static device globals; no runtime allocation) ----
__device__ __align__(16) __half g_x_hi[(size_t)BS * D];
__device__ __align__(16) __half g_x_lo[(size_t)BS * D];
__device__ __align__(16) __half g_wt_hi[(size_t)3 * H * E * D]; // [which][h*E+e][k]
__device__ __align__(16) __half g_wt_lo[(size_t)3 * H * E * D];
__device__ __align__(16) __half g_wo_hi[(size_t)D * D];         // [n][k]
__device__ __align__(16) __half g_qkvb_hi[(size_t)3 * H * BS * E]; // [which][h][b*S+s][e]
__device__ __align__(16) __half g_qkvb_lo[(size_t)3 * H * BS * E]; // only K-lo used
__device__ __align__(16) __half g_att_hi[(size_t)BS * D];       // [b*S+s][h*E+e]

// ======================= helpers =======================
__device__ __forceinline__ uint32_t smem_u32(const void* p) {
    uint32_t a;
    asm("{ .reg .u64 t; cvta.to.shared.u64 t, %1; cvt.u32.u64 %0, t; }" : "=r"(a) : "l"(p));
    return a;
}
// swizzled offset within a tile of 128-byte rows: row r, 16B-chunk c16 (0..7)
__device__ __forceinline__ uint32_t sw_off(uint32_t r, uint32_t c16) {
    return (r << 7) + (((c16 ^ r) & 7u) << 4);
}
__device__ __forceinline__ void ldsm4(uint32_t* r, uint32_t a) {
    asm volatile("ldmatrix.sync.aligned.m8n8.x4.shared.b16 {%0,%1,%2,%3}, [%4];"
        : "=r"(r[0]), "=r"(r[1]), "=r"(r[2]), "=r"(r[3]) : "r"(a));
}
__device__ __forceinline__ void ldsm4t(uint32_t* r, uint32_t a) {
    asm volatile("ldmatrix.sync.aligned.m8n8.x4.trans.shared.b16 {%0,%1,%2,%3}, [%4];"
        : "=r"(r[0]), "=r"(r[1]), "=r"(r[2]), "=r"(r[3]) : "r"(a));
}
__device__ __forceinline__ void mma16816(float* c, const uint32_t* a, uint32_t b0, uint32_t b1) {
    asm volatile("mma.sync.aligned.m16n8k16.row.col.f32.f16.f16.f32 "
        "{%0,%1,%2,%3}, {%4,%5,%6,%7}, {%8,%9}, {%0,%1,%2,%3};"
        : "+f"(c[0]), "+f"(c[1]), "+f"(c[2]), "+f"(c[3])
        : "r"(a[0]), "r"(a[1]), "r"(a[2]), "r"(a[3]), "r"(b0), "r"(b1));
}
__device__ __forceinline__ void split2(float x, float y, uint32_t& hi, uint32_t& lo) {
    __half2 h = __floats2half2_rn(x, y);
    float hx = __low2float(h), hy = __high2float(h);
    __half2 l = __floats2half2_rn(x - hx, y - hy);
    hi = *(uint32_t*)&h; lo = *(uint32_t*)&l;
}
__device__ __forceinline__ uint32_t pack2(float x, float y) {
    __half2 h = __floats2half2_rn(x, y);
    return *(uint32_t*)&h;
}
#define CP_COMMIT()  asm volatile("cp.async.commit_group;" ::: "memory")
#define CP_WAIT1()   asm volatile("cp.async.wait_group 1;" ::: "memory")
#define CP_WAIT0()   asm volatile("cp.async.wait_group 0;" ::: "memory")

// cp.async a tile of R rows x 64 fp16 (128B/row) into swizzled smem (256 threads)
template<int R>
__device__ __forceinline__ void cpa_tile(const __half* __restrict__ g, int ldg,
                                         uint32_t sdst, int t)
{
    #pragma unroll
    for (int i = 0; i < (R * 8) / 256; i++) {
        int f = i * 256 + t;
        uint32_t r = (uint32_t)(f >> 3), c = (uint32_t)(f & 7);
        asm volatile("cp.async.cg.shared.global [%0], [%1], 16;"
            :: "r"(sdst + sw_off(r, c)), "l"(g + (size_t)r * ldg + c * 8));
    }
}

// ======================= fused prep: fp32 -> fp16 hi/lo =======================
__global__ void prep_kernel(const float* __restrict__ x,
                            const float* __restrict__ Wq, const float* __restrict__ Wk,
                            const float* __restrict__ Wv, const float* __restrict__ Wo)
{
    int i = blockIdx.x * 256 + threadIdx.x;
    float v;
    if (i < XN) {
        v = x[i];
        __half hv = __float2half_rn(v);
        g_x_hi[i] = hv;
        g_x_lo[i] = __float2half_rn(v - __half2float(hv));
    } else if (i < XN + 3 * HED) {
        int i2 = i - XN;
        int w = i2 / HED, r2 = i2 % HED;
        int k = r2 % D, row = r2 / D;
        int h = row / E, e = row % E;
        const float* W = (w == 0) ? Wq : (w == 1) ? Wk : Wv;
        v = W[((size_t)h * D + k) * E + e];
        __half hv = __float2half_rn(v);
        g_wt_hi[i2] = hv;
        g_wt_lo[i2] = __float2half_rn(v - __half2float(hv));
    } else if (i < XN + 3 * HED + D * D) {
        int i3 = i - XN - 3 * HED;
        int k = i3 % D, n = i3 / D;
        g_wo_hi[i3] = __float2half_rn(Wo[(size_t)k * D + n]);
    }
}

// ======================= GEMM core: CTA 128x64, 8 warps (4x2), warp tile 32x32 ==========
// products: Ah*Bh always; + Al*Bh if use_alo; + Ah*Bl if use_blo
struct Acc64 { float a[2][4][4]; };
#define G_STAGE 49152

__device__ __forceinline__ void gemm_core(
    const __half* __restrict__ Ah_g, const __half* __restrict__ Al_g, int lda,
    const __half* __restrict__ Bh_g, const __half* __restrict__ Bl_g, int ldb,
    uint32_t sb, int t, Acc64& C, bool use_alo, bool use_blo)
{
    const int lane = t & 31, wid = t >> 5;
    const int wm = (wid >> 1) * 32, wn = (wid & 1) * 32;

    cpa_tile<128>(Ah_g, lda, sb, t);
    if (use_alo) cpa_tile<128>(Al_g, lda, sb + 16384, t);
    cpa_tile<64>(Bh_g, ldb, sb + 32768, t);
    if (use_blo) cpa_tile<64>(Bl_g, ldb, sb + 40960, t);
    CP_COMMIT();

    const uint32_t a_row  = (uint32_t)(wm + (lane & 15));
    const uint32_t a_chi  = (uint32_t)((lane >> 4) & 1);
    const uint32_t b_row0 = (uint32_t)(wn + (lane & 7) + ((lane & 16) >> 1));
    const uint32_t b_chi  = (uint32_t)((lane >> 3) & 1);

    #pragma unroll 1
    for (int c = 0; c < 12; c++) {
        if (c + 1 < 12) {
            uint32_t st = sb + (uint32_t)((c + 1) & 1) * G_STAGE;
            cpa_tile<128>(Ah_g + (c + 1) * 64, lda, st, t);
            if (use_alo) cpa_tile<128>(Al_g + (c + 1) * 64, lda, st + 16384, t);
            cpa_tile<64>(Bh_g + (c + 1) * 64, ldb, st + 32768, t);
            if (use_blo) cpa_tile<64>(Bl_g + (c + 1) * 64, ldb, st + 40960, t);
            CP_COMMIT();
            CP_WAIT1();
        } else {
            CP_WAIT0();
        }
        __syncthreads();

        const uint32_t cs = sb + (uint32_t)(c & 1) * G_STAGE;
        const uint32_t uAh = cs, uAl = cs + 16384, uBh = cs + 32768, uBl = cs + 40960;

        #pragma unroll
        for (int ks = 0; ks < 4; ks++) {
            const uint32_t c16a = (uint32_t)(ks * 2) + a_chi;
            const uint32_t c16b = (uint32_t)(ks * 2) + b_chi;
            uint32_t ah0[4], ah1[4], al0[4], al1[4];
            ldsm4(ah0, uAh + sw_off(a_row, c16a));
            ldsm4(ah1, uAh + sw_off(a_row + 16, c16a));
            if (use_alo) {
                ldsm4(al0, uAl + sw_off(a_row, c16a));
                ldsm4(al1, uAl + sw_off(a_row + 16, c16a));
            }
            #pragma unroll
            for (int np = 0; np < 2; np++) {
                uint32_t bh[4];
                ldsm4(bh, uBh + sw_off(b_row0 + np * 16, c16b));
                mma16816(C.a[0][2*np],   ah0, bh[0], bh[1]);
                mma16816(C.a[0][2*np+1], ah0, bh[2], bh[3]);
                mma16816(C.a[1][2*np],   ah1, bh[0], bh[1]);
                mma16816(C.a[1][2*np+1], ah1, bh[2], bh[3]);
                if (use_alo) {
                    mma16816(C.a[0][2*np],   al0, bh[0], bh[1]);
                    mma16816(C.a[0][2*np+1], al0, bh[2], bh[3]);
                    mma16816(C.a[1][2*np],   al1, bh[0], bh[1]);
                    mma16816(C.a[1][2*np+1], al1, bh[2], bh[3]);
                }
                if (use_blo) {
                    uint32_t bl[4];
                    ldsm4(bl, uBl + sw_off(b_row0 + np * 16, c16b));
                    mma16816(C.a[0][2*np],   ah0, bl[0], bl[1]);
                    mma16816(C.a[0][2*np+1], ah0, bl[2], bl[3]);
                    mma16816(C.a[1][2*np],   ah1, bl[0], bl[1]);
                    mma16816(C.a[1][2*np+1], ah1, bl[2], bl[3]);
                }
            }
        }
        __syncthreads();
    }
}

// ======================= QKV GEMM kernel: CTA 128(m) x 64(one head) =======================
// Q,K: 3-product (feed logits).  V: 1-product (relative tolerance).
__global__ __launch_bounds__(256, 2) void qkv_mma_kernel(
    const float* __restrict__ bq, const float* __restrict__ bk, const float* __restrict__ bv)
{
    extern __shared__ __align__(16) char smem[];
    const uint32_t sb = smem_u32(smem);
    const int t = threadIdx.x, lane = t & 31, wid = t >> 5;
    const int m0 = blockIdx.x * 128;
    const int zz = blockIdx.y;             // 0..35
    const int which = zz / H;
    const int h = zz % H;

    Acc64 C;
    #pragma unroll
    for (int i = 0; i < 2; i++)
        #pragma unroll
        for (int j = 0; j < 4; j++)
            C.a[i][j][0] = C.a[i][j][1] = C.a[i][j][2] = C.a[i][j][3] = 0.f;

    const bool full = (which != 2);
    gemm_core(g_x_hi + (size_t)m0 * D, g_x_lo + (size_t)m0 * D, D,
              g_wt_hi + ((size_t)which * H + h) * E * D,
              g_wt_lo + ((size_t)which * H + h) * E * D, D,
              sb, t, C, full, full);

    const float* bias = (which == 0) ? bq : (which == 1) ? bk : bv;
    const int g = lane >> 2, j2 = (lane & 3) * 2;
    const int wm = (wid >> 1) * 32, wn = (wid & 1) * 32;
    const size_t obase = ((size_t)which * H + h) * BS * E;
    const bool need_lo = (which == 1);   // only K-lo is consumed (QK^T 2-product)

    #pragma unroll
    for (int mi = 0; mi < 2; mi++) {
        const int mA = m0 + wm + mi * 16 + g;
        #pragma unroll
        for (int nt = 0; nt < 4; nt++) {
            const int e = wn + nt * 8 + j2;
            const float b0f = bias[h * E + e], b1f = bias[h * E + e + 1];
            uint32_t hi, lo;
            split2(C.a[mi][nt][0] + b0f, C.a[mi][nt][1] + b1f, hi, lo);
            *(uint32_t*)(g_qkvb_hi + obase + (size_t)mA * E + e) = hi;
            if (need_lo) *(uint32_t*)(g_qkvb_lo + obase + (size_t)mA * E + e) = lo;
            split2(C.a[mi][nt][2] + b0f, C.a[mi][nt][3] + b1f, hi, lo);
            *(uint32_t*)(g_qkvb_hi + obase + (size_t)(mA + 8) * E + e) = hi;
            if (need_lo) *(uint32_t*)(g_qkvb_lo + obase + (size_t)(mA + 8) * E + e) = lo;
        }
    }
}

// ======================= output projection: CTA 128(m) x 64(n), 1-product ===============
__global__ __launch_bounds__(256, 2) void proj_mma_kernel(
    const float* __restrict__ bo, float* __restrict__ out)
{
    extern __shared__ __align__(16) char smem[];
    const uint32_t sb = smem_u32(smem);
    const int t = threadIdx.x, lane = t & 31, wid = t >> 5;
    const int m0 = blockIdx.x * 128;
    const int n0 = blockIdx.y * 64;

    Acc64 C;
    #pragma unroll
    for (int i = 0; i < 2; i++)
        #pragma unroll
        for (int j = 0; j < 4; j++)
            C.a[i][j][0] = C.a[i][j][1] = C.a[i][j][2] = C.a[i][j][3] = 0.f;

    gemm_core(g_att_hi + (size_t)m0 * D, g_att_hi + (size_t)m0 * D, D,
              g_wo_hi + (size_t)n0 * D, g_wo_hi + (size_t)n0 * D, D,
              sb, t, C, false, false);

    const int g = lane >> 2, j2 = (lane & 3) * 2;
    const int wm = (wid >> 1) * 32, wn = (wid & 1) * 32;

    #pragma unroll
    for (int mi = 0; mi < 2; mi++) {
        const int mA = m0 + wm + mi * 16 + g;
        #pragma unroll
        for (int nt = 0; nt < 4; nt++) {
            const int n = n0 + wn + nt * 8 + j2;
            const float b0f = bo[n], b1f = bo[n + 1];
            float2 v0 = { C.a[mi][nt][0] + b0f, C.a[mi][nt][1] + b1f };
            float2 v1 = { C.a[mi][nt][2] + b0f, C.a[mi][nt][3] + b1f };
            *(float2*)(out + (size_t)mA * D + n) = v0;
            *(float2*)(out + (size_t)(mA + 8) * D + n) = v1;
        }
    }
}

// ======================= flash attention =======================
// 256 threads, 8 warps x 16 q-rows = 128-row q tile; kv chunks of 64, 32 chunks.
// S = QK^T: 2-product (qh*kh + qh*kl).  PV: 1-product (P plain fp16).
#define A_STAGE 24576
#define A_KV    16384
__global__ __launch_bounds__(256, 2) void attn_kernel(const float* __restrict__ mask_all)
{
    extern __shared__ __align__(16) char smem[];
    const uint32_t sb = smem_u32(smem);

    const int q0 = blockIdx.x * 128;
    const int hb = blockIdx.y;
    const int h = hb / B, b = hb % B;

    const __half* Qh_g = g_qkvb_hi + ((size_t)0 * H + h) * BS * E + (size_t)(b * S + q0) * E;
    const __half* Kh_g = g_qkvb_hi + ((size_t)1 * H + h) * BS * E + (size_t)b * S * E;
    const __half* Kl_g = g_qkvb_lo + ((size_t)1 * H + h) * BS * E + (size_t)b * S * E;
    const __half* Vh_g = g_qkvb_hi + ((size_t)2 * H + h) * BS * E + (size_t)b * S * E;
    const float* mask = mask_all + (size_t)(h * B + b) * S * S;

    const int t = threadIdx.x, lane = t & 31, wid = t >> 5;
    const int g = lane >> 2, j2 = (lane & 3) * 2;
    const int r0 = wid * 16;

    // Q -> resident smem region (16K)
    cpa_tile<128>(Qh_g, E, sb, t);
    CP_COMMIT();
    // kv chunk 0 -> stage 0
    cpa_tile<64>(Kh_g, E, sb + A_KV, t);
    cpa_tile<64>(Kl_g, E, sb + A_KV + 8192, t);
    cpa_tile<64>(Vh_g, E, sb + A_KV + 16384, t);
    CP_COMMIT();

    float m_a = -INFINITY, m_b = -INFINITY, l_a = 0.f, l_b = 0.f;
    float o[8][4];
    #pragma unroll
    for (int et = 0; et < 8; et++)
        o[et][0] = o[et][1] = o[et][2] = o[et][3] = 0.f;

    const uint32_t a_row  = (uint32_t)(r0 + (lane & 15));
    const uint32_t a_chi  = (uint32_t)((lane >> 4) & 1);
    const uint32_t b_row0 = (uint32_t)((lane & 7) + ((lane & 16) >> 1));
    const uint32_t b_chi  = (uint32_t)((lane >> 3) & 1);
    const uint32_t v_row  = (uint32_t)(lane & 15);
    const uint32_t v_chi  = (uint32_t)((lane >> 4) & 1);

    #pragma unroll 1
    for (int jc = 0; jc < 32; jc++) {
        const int j0 = jc * 64;

        // mask loads initialize S accumulators; overlap pipeline wait
        float s[8][4];
        const float* mra = mask + (size_t)(q0 + r0 + g) * S + j0 + j2;
        const float* mrb = mra + 8 * S;
        #pragma unroll
        for (int nt = 0; nt < 8; nt++) {
            float2 ma = *(const float2*)(mra + nt * 8);
            float2 mb = *(const float2*)(mrb + nt * 8);
            s[nt][0] = ma.x; s[nt][1] = ma.y; s[nt][2] = mb.x; s[nt][3] = mb.y;
        }

        if (jc + 1 < 32) {
            const uint32_t ns = sb + A_KV + (uint32_t)((jc + 1) & 1) * A_STAGE;
            const size_t go = (size_t)(j0 + 64) * E;
            cpa_tile<64>(Kh_g + go, E, ns, t);
            cpa_tile<64>(Kl_g + go, E, ns + 8192, t);
            cpa_tile<64>(Vh_g + go, E, ns + 16384, t);
            CP_COMMIT();
            CP_WAIT1();
        } else {
            CP_WAIT0();
        }
        __syncthreads();

        const uint32_t cs = sb + A_KV + (uint32_t)(jc & 1) * A_STAGE;
        const uint32_t uKh = cs, uKl = cs + 8192, uVh = cs + 16384;

        // ---- S += Q K^T (2-product: qh*kh + qh*kl) ----
        #pragma unroll
        for (int ks = 0; ks < 4; ks++) {
            const uint32_t c16a = (uint32_t)(ks * 2) + a_chi;
            const uint32_t c16b = (uint32_t)(ks * 2) + b_chi;
            uint32_t qh[4];
            ldsm4(qh, sb + sw_off(a_row, c16a));
            #pragma unroll
            for (int np = 0; np < 4; np++) {
                uint32_t bh[4], bl[4];
                const uint32_t bo_ = sw_off(b_row0 + np * 16, c16b);
                ldsm4(bh, uKh + bo_);
                ldsm4(bl, uKl + bo_);
                mma16816(s[2*np],   qh, bh[0], bh[1]);
                mma16816(s[2*np+1], qh, bh[2], bh[3]);
                mma16816(s[2*np],   qh, bl[0], bl[1]);
                mma16816(s[2*np+1], qh, bl[2], bl[3]);
            }
        }

        // ---- online softmax (rows g and g+8) ----
        float mxa = -INFINITY, mxb = -INFINITY;
        #pragma unroll
        for (int nt = 0; nt < 8; nt++) {
            mxa = fmaxf(mxa, fmaxf(s[nt][0], s[nt][1]));
            mxb = fmaxf(mxb, fmaxf(s[nt][2], s[nt][3]));
        }
        mxa = fmaxf(mxa, __shfl_xor_sync(0xffffffffu, mxa, 1));
        mxa = fmaxf(mxa, __shfl_xor_sync(0xffffffffu, mxa, 2));
        mxb = fmaxf(mxb, __shfl_xor_sync(0xffffffffu, mxb, 1));
        mxb = fmaxf(mxb, __shfl_xor_sync(0xffffffffu, mxb, 2));

        const float mna = fmaxf(m_a, mxa), mnb = fmaxf(m_b, mxb);
        const float aa = __expf(m_a - mna), ab = __expf(m_b - mnb);
        float sa = 0.f, sb2 = 0.f;
        #pragma unroll
        for (int nt = 0; nt < 8; nt++) {
            s[nt][0] = __expf(s[nt][0] - mna); sa += s[nt][0];
            s[nt][1] = __expf(s[nt][1] - mna); sa += s[nt][1];
            s[nt][2] = __expf(s[nt][2] - mnb); sb2 += s[nt][2];
            s[nt][3] = __expf(s[nt][3] - mnb); sb2 += s[nt][3];
        }
        sa  += __shfl_xor_sync(0xffffffffu, sa, 1);
        sa  += __shfl_xor_sync(0xffffffffu, sa, 2);
        sb2 += __shfl_xor_sync(0xffffffffu, sb2, 1);
        sb2 += __shfl_xor_sync(0xffffffffu, sb2, 2);
        l_a = l_a * aa + sa; l_b = l_b * ab + sb2;
        m_a = mna; m_b = mnb;
        #pragma unroll
        for (int et = 0; et < 8; et++) {
            o[et][0] *= aa; o[et][1] *= aa;
            o[et][2] *= ab; o[et][3] *= ab;
        }

        // ---- O += P V (P plain fp16: 1-product) ----
        #pragma unroll
        for (int ks2 = 0; ks2 < 4; ks2++) {
            const int nt0 = 2 * ks2, nt1 = nt0 + 1;
            uint32_t a_p[4];
            a_p[0] = pack2(s[nt0][0], s[nt0][1]);
            a_p[1] = pack2(s[nt0][2], s[nt0][3]);
            a_p[2] = pack2(s[nt1][0], s[nt1][1]);
            a_p[3] = pack2(s[nt1][2], s[nt1][3]);
            #pragma unroll
            for (int ep = 0; ep < 4; ep++) {
                uint32_t vh[4];
                ldsm4t(vh, uVh + sw_off(v_row + ks2 * 16, (uint32_t)(ep * 2) + v_chi));
                mma16816(o[2*ep],   a_p, vh[0], vh[1]);
                mma16816(o[2*ep+1], a_p, vh[2], vh[3]);
            }
        }
        __syncthreads();
    }

    // ---- epilogue: normalize, pack fp16, concat-head layout ----
    const float ia = 1.f / l_a, ib = 1.f / l_b;
    const int rowA = q0 + r0 + g, rowB = rowA + 8;
    #pragma unroll
    for (int et = 0; et < 8; et++) {
        const size_t col = (size_t)h * E + et * 8 + j2;
        *(uint32_t*)(g_att_hi + (size_t)(b * S + rowA) * D + col) =
            pack2(o[et][0] * ia, o[et][1] * ia);
        *(uint32_t*)(g_att_hi + (size_t)(b * S + rowB) * D + col) =
            pack2(o[et][2] * ib, o[et][3] * ib);
    }
}

// ======================= Launch =======================
extern "C" void kernel_launch(void* const* d_in, const int* in_sizes, int n_in,
                              void* d_out, int out_size)
{
    const float* x    = (const float*)d_in[0];
    const float* mask = (const float*)d_in[1];
    const float* Wq   = (const float*)d_in[2];
    const float* bq   = (const float*)d_in[3];
    const float* Wk   = (const float*)d_in[4];
    const float* bk   = (const float*)d_in[5];
    const float* Wv   = (const float*)d_in[6];
    const float* bv   = (const float*)d_in[7];
    const float* Wo   = (const float*)d_in[8];
    const float* bo   = (const float*)d_in[9];

    const int smem_gemm = 2 * G_STAGE;          // 98,304 B
    const int smem_attn = A_KV + 2 * A_STAGE;   // 65,536 B
    cudaFuncSetAttribute(qkv_mma_kernel,  cudaFuncAttributeMaxDynamicSharedMemorySize, smem_gemm);
    cudaFuncSetAttribute(proj_mma_kernel, cudaFuncAttributeMaxDynamicSharedMemorySize, smem_gemm);
    cudaFuncSetAttribute(attn_kernel,     cudaFuncAttributeMaxDynamicSharedMemorySize, smem_attn);

    const int prep_n = XN + 3 * HED + D * D;
    prep_kernel<<< (prep_n + 255) / 256, 256 >>>(x, Wq, Wk, Wv, Wo);

    qkv_mma_kernel <<< dim3(BS / 128, 3 * H), 256, smem_gemm >>>(bq, bk, bv);
    attn_kernel    <<< dim3(S / 128, H * B), 256, smem_attn >>>(mask);
    proj_mma_kernel<<< dim3(BS / 128, D / 64), 256, smem_gemm >>>(bo, (float*)d_out);
}

// round 11
// speedup vs baseline: 1.2629x; 1.0087x over previous
#include <cuda_runtime.h>
#include <cuda_fp16.h>
#include <math.h>
#include <stdint.h>

#define B 2
#define S 2048
#define D 768
#define H 12
#define E 64
#define BS (B*S)   // 4096
#define XN (BS*D)
#define HED (H*E*D)

// ---- scratch (static device globals; no runtime allocation) ----
__device__ __align__(16) __half g_x_hi[(size_t)BS * D];
__device__ __align__(16) __half g_x_lo[(size_t)BS * D];
__device__ __align__(16) __half g_wt_hi[(size_t)3 * H * E * D]; // [which][h*E+e][k]
__device__ __align__(16) __half g_wt_lo[(size_t)3 * H * E * D];
__device__ __align__(16) __half g_wo_hi[(size_t)D * D];         // [n][k]
__device__ __align__(16) __half g_qkvb_hi[(size_t)3 * H * BS * E]; // [which][h][b*S+s][e]
__device__ __align__(16) __half g_qkvb_lo[(size_t)3 * H * BS * E]; // only K-lo used
__device__ __align__(16) __half g_att_hi[(size_t)BS * D];       // [b*S+s][h*E+e]

// ======================= helpers =======================
__device__ __forceinline__ uint32_t smem_u32(const void* p) {
    uint32_t a;
    asm("{ .reg .u64 t; cvta.to.shared.u64 t, %1; cvt.u32.u64 %0, t; }" : "=r"(a) : "l"(p));
    return a;
}
// swizzled offset within a tile of 128-byte rows: row r, 16B-chunk c16 (0..7)
__device__ __forceinline__ uint32_t sw_off(uint32_t r, uint32_t c16) {
    return (r << 7) + (((c16 ^ r) & 7u) << 4);
}
__device__ __forceinline__ void ldsm4(uint32_t* r, uint32_t a) {
    asm volatile("ldmatrix.sync.aligned.m8n8.x4.shared.b16 {%0,%1,%2,%3}, [%4];"
        : "=r"(r[0]), "=r"(r[1]), "=r"(r[2]), "=r"(r[3]) : "r"(a));
}
__device__ __forceinline__ void ldsm4t(uint32_t* r, uint32_t a) {
    asm volatile("ldmatrix.sync.aligned.m8n8.x4.trans.shared.b16 {%0,%1,%2,%3}, [%4];"
        : "=r"(r[0]), "=r"(r[1]), "=r"(r[2]), "=r"(r[3]) : "r"(a));
}
__device__ __forceinline__ void mma16816(float* c, const uint32_t* a, uint32_t b0, uint32_t b1) {
    asm volatile("mma.sync.aligned.m16n8k16.row.col.f32.f16.f16.f32 "
        "{%0,%1,%2,%3}, {%4,%5,%6,%7}, {%8,%9}, {%0,%1,%2,%3};"
        : "+f"(c[0]), "+f"(c[1]), "+f"(c[2]), "+f"(c[3])
        : "r"(a[0]), "r"(a[1]), "r"(a[2]), "r"(a[3]), "r"(b0), "r"(b1));
}
__device__ __forceinline__ void split2(float x, float y, uint32_t& hi, uint32_t& lo) {
    __half2 h = __floats2half2_rn(x, y);
    float hx = __low2float(h), hy = __high2float(h);
    __half2 l = __floats2half2_rn(x - hx, y - hy);
    hi = *(uint32_t*)&h; lo = *(uint32_t*)&l;
}
__device__ __forceinline__ uint32_t pack2(float x, float y) {
    __half2 h = __floats2half2_rn(x, y);
    return *(uint32_t*)&h;
}
#define CP_COMMIT()  asm volatile("cp.async.commit_group;" ::: "memory")
#define CP_WAIT1()   asm volatile("cp.async.wait_group 1;" ::: "memory")
#define CP_WAIT0()   asm volatile("cp.async.wait_group 0;" ::: "memory")

// cp.async a tile of R rows x 64 fp16 (128B/row) into swizzled smem (256 threads)
template<int R>
__device__ __forceinline__ void cpa_tile(const __half* __restrict__ g, int ldg,
                                         uint32_t sdst, int t)
{
    #pragma unroll
    for (int i = 0; i < (R * 8) / 256; i++) {
        int f = i * 256 + t;
        uint32_t r = (uint32_t)(f >> 3), c = (uint32_t)(f & 7);
        asm volatile("cp.async.cg.shared.global [%0], [%1], 16;"
            :: "r"(sdst + sw_off(r, c)), "l"(g + (size_t)r * ldg + c * 8));
    }
}

// ======================= fused prep: fp32 -> fp16 hi/lo =======================
__global__ void prep_kernel(const float* __restrict__ x,
                            const float* __restrict__ Wq, const float* __restrict__ Wk,
                            const float* __restrict__ Wv, const float* __restrict__ Wo)
{
    int i = blockIdx.x * 256 + threadIdx.x;
    float v;
    if (i < XN) {
        v = x[i];
        __half hv = __float2half_rn(v);
        g_x_hi[i] = hv;
        g_x_lo[i] = __float2half_rn(v - __half2float(hv));
    } else if (i < XN + 3 * HED) {
        int i2 = i - XN;
        int w = i2 / HED, r2 = i2 % HED;
        int k = r2 % D, row = r2 / D;
        int h = row / E, e = row % E;
        const float* W = (w == 0) ? Wq : (w == 1) ? Wk : Wv;
        v = W[((size_t)h * D + k) * E + e];
        __half hv = __float2half_rn(v);
        g_wt_hi[i2] = hv;
        g_wt_lo[i2] = __float2half_rn(v - __half2float(hv));
    } else if (i < XN + 3 * HED + D * D) {
        int i3 = i - XN - 3 * HED;
        int k = i3 % D, n = i3 / D;
        g_wo_hi[i3] = __float2half_rn(Wo[(size_t)k * D + n]);
    }
}

// ======================= GEMM core: CTA 128x64, 8 warps (4x2), warp tile 32x32 ==========
// products: Ah*Bh always; + Al*Bh if use_alo; + Ah*Bl if use_blo.
// MMA issue order restructured into hi / alo / blo passes: same-accumulator
// writes are >= 8 MMAs apart (was 4), per-acc contribution order unchanged
// (bit-identical results vs interleaved form).
struct Acc64 { float a[2][4][4]; };
#define G_STAGE 49152

__device__ __forceinline__ void gemm_core(
    const __half* __restrict__ Ah_g, const __half* __restrict__ Al_g, int lda,
    const __half* __restrict__ Bh_g, const __half* __restrict__ Bl_g, int ldb,
    uint32_t sb, int t, Acc64& C, bool use_alo, bool use_blo)
{
    const int lane = t & 31, wid = t >> 5;
    const int wm = (wid >> 1) * 32, wn = (wid & 1) * 32;

    cpa_tile<128>(Ah_g, lda, sb, t);
    if (use_alo) cpa_tile<128>(Al_g, lda, sb + 16384, t);
    cpa_tile<64>(Bh_g, ldb, sb + 32768, t);
    if (use_blo) cpa_tile<64>(Bl_g, ldb, sb + 40960, t);
    CP_COMMIT();

    const uint32_t a_row  = (uint32_t)(wm + (lane & 15));
    const uint32_t a_chi  = (uint32_t)((lane >> 4) & 1);
    const uint32_t b_row0 = (uint32_t)(wn + (lane & 7) + ((lane & 16) >> 1));
    const uint32_t b_chi  = (uint32_t)((lane >> 3) & 1);

    #pragma unroll 1
    for (int c = 0; c < 12; c++) {
        if (c + 1 < 12) {
            uint32_t st = sb + (uint32_t)((c + 1) & 1) * G_STAGE;
            cpa_tile<128>(Ah_g + (c + 1) * 64, lda, st, t);
            if (use_alo) cpa_tile<128>(Al_g + (c + 1) * 64, lda, st + 16384, t);
            cpa_tile<64>(Bh_g + (c + 1) * 64, ldb, st + 32768, t);
            if (use_blo) cpa_tile<64>(Bl_g + (c + 1) * 64, ldb, st + 40960, t);
            CP_COMMIT();
            CP_WAIT1();
        } else {
            CP_WAIT0();
        }
        __syncthreads();

        const uint32_t cs = sb + (uint32_t)(c & 1) * G_STAGE;
        const uint32_t uAh = cs, uAl = cs + 16384, uBh = cs + 32768, uBl = cs + 40960;

        #pragma unroll
        for (int ks = 0; ks < 4; ks++) {
            const uint32_t c16a = (uint32_t)(ks * 2) + a_chi;
            const uint32_t c16b = (uint32_t)(ks * 2) + b_chi;
            // --- load A-hi and BOTH B-hi fragments up front ---
            uint32_t ah0[4], ah1[4], bh0[4], bh1[4];
            ldsm4(ah0, uAh + sw_off(a_row, c16a));
            ldsm4(ah1, uAh + sw_off(a_row + 16, c16a));
            ldsm4(bh0, uBh + sw_off(b_row0, c16b));
            ldsm4(bh1, uBh + sw_off(b_row0 + 16, c16b));
            // --- hi pass: 8 MMAs, 8 distinct accumulators ---
            mma16816(C.a[0][0], ah0, bh0[0], bh0[1]);
            mma16816(C.a[0][1], ah0, bh0[2], bh0[3]);
            mma16816(C.a[1][0], ah1, bh0[0], bh0[1]);
            mma16816(C.a[1][1], ah1, bh0[2], bh0[3]);
            mma16816(C.a[0][2], ah0, bh1[0], bh1[1]);
            mma16816(C.a[0][3], ah0, bh1[2], bh1[3]);
            mma16816(C.a[1][2], ah1, bh1[0], bh1[1]);
            mma16816(C.a[1][3], ah1, bh1[2], bh1[3]);
            // --- alo pass ---
            if (use_alo) {
                uint32_t al0[4], al1[4];
                ldsm4(al0, uAl + sw_off(a_row, c16a));
                ldsm4(al1, uAl + sw_off(a_row + 16, c16a));
                mma16816(C.a[0][0], al0, bh0[0], bh0[1]);
                mma16816(C.a[0][1], al0, bh0[2], bh0[3]);
                mma16816(C.a[1][0], al1, bh0[0], bh0[1]);
                mma16816(C.a[1][1], al1, bh0[2], bh0[3]);
                mma16816(C.a[0][2], al0, bh1[0], bh1[1]);
                mma16816(C.a[0][3], al0, bh1[2], bh1[3]);
                mma16816(C.a[1][2], al1, bh1[0], bh1[1]);
                mma16816(C.a[1][3], al1, bh1[2], bh1[3]);
            }
            // --- blo pass ---
            if (use_blo) {
                uint32_t bl0[4], bl1[4];
                ldsm4(bl0, uBl + sw_off(b_row0, c16b));
                ldsm4(bl1, uBl + sw_off(b_row0 + 16, c16b));
                mma16816(C.a[0][0], ah0, bl0[0], bl0[1]);
                mma16816(C.a[0][1], ah0, bl0[2], bl0[3]);
                mma16816(C.a[1][0], ah1, bl0[0], bl0[1]);
                mma16816(C.a[1][1], ah1, bl0[2], bl0[3]);
                mma16816(C.a[0][2], ah0, bl1[0], bl1[1]);
                mma16816(C.a[0][3], ah0, bl1[2], bl1[3]);
                mma16816(C.a[1][2], ah1, bl1[0], bl1[1]);
                mma16816(C.a[1][3], ah1, bl1[2], bl1[3]);
            }
        }
        __syncthreads();
    }
}

// ======================= QKV GEMM kernel: CTA 128(m) x 64(one head) =======================
// Q,K: 3-product (feed logits).  V: 1-product (relative tolerance).
__global__ __launch_bounds__(256, 2) void qkv_mma_kernel(
    const float* __restrict__ bq, const float* __restrict__ bk, const float* __restrict__ bv)
{
    extern __shared__ __align__(16) char smem[];
    const uint32_t sb = smem_u32(smem);
    const int t = threadIdx.x, lane = t & 31, wid = t >> 5;
    const int m0 = blockIdx.x * 128;
    const int zz = blockIdx.y;             // 0..35
    const int which = zz / H;
    const int h = zz % H;

    Acc64 C;
    #pragma unroll
    for (int i = 0; i < 2; i++)
        #pragma unroll
        for (int j = 0; j < 4; j++)
            C.a[i][j][0] = C.a[i][j][1] = C.a[i][j][2] = C.a[i][j][3] = 0.f;

    const bool full = (which != 2);
    gemm_core(g_x_hi + (size_t)m0 * D, g_x_lo + (size_t)m0 * D, D,
              g_wt_hi + ((size_t)which * H + h) * E * D,
              g_wt_lo + ((size_t)which * H + h) * E * D, D,
              sb, t, C, full, full);

    const float* bias = (which == 0) ? bq : (which == 1) ? bk : bv;
    const int g = lane >> 2, j2 = (lane & 3) * 2;
    const int wm = (wid >> 1) * 32, wn = (wid & 1) * 32;
    const size_t obase = ((size_t)which * H + h) * BS * E;
    const bool need_lo = (which == 1);   // only K-lo is consumed (QK^T 2-product)

    #pragma unroll
    for (int mi = 0; mi < 2; mi++) {
        const int mA = m0 + wm + mi * 16 + g;
        #pragma unroll
        for (int nt = 0; nt < 4; nt++) {
            const int e = wn + nt * 8 + j2;
            const float b0f = bias[h * E + e], b1f = bias[h * E + e + 1];
            uint32_t hi, lo;
            split2(C.a[mi][nt][0] + b0f, C.a[mi][nt][1] + b1f, hi, lo);
            *(uint32_t*)(g_qkvb_hi + obase + (size_t)mA * E + e) = hi;
            if (need_lo) *(uint32_t*)(g_qkvb_lo + obase + (size_t)mA * E + e) = lo;
            split2(C.a[mi][nt][2] + b0f, C.a[mi][nt][3] + b1f, hi, lo);
            *(uint32_t*)(g_qkvb_hi + obase + (size_t)(mA + 8) * E + e) = hi;
            if (need_lo) *(uint32_t*)(g_qkvb_lo + obase + (size_t)(mA + 8) * E + e) = lo;
        }
    }
}

// ======================= output projection: CTA 128(m) x 64(n), 1-product ===============
__global__ __launch_bounds__(256, 2) void proj_mma_kernel(
    const float* __restrict__ bo, float* __restrict__ out)
{
    extern __shared__ __align__(16) char smem[];
    const uint32_t sb = smem_u32(smem);
    const int t = threadIdx.x, lane = t & 31, wid = t >> 5;
    const int m0 = blockIdx.x * 128;
    const int n0 = blockIdx.y * 64;

    Acc64 C;
    #pragma unroll
    for (int i = 0; i < 2; i++)
        #pragma unroll
        for (int j = 0; j < 4; j++)
            C.a[i][j][0] = C.a[i][j][1] = C.a[i][j][2] = C.a[i][j][3] = 0.f;

    gemm_core(g_att_hi + (size_t)m0 * D, g_att_hi + (size_t)m0 * D, D,
              g_wo_hi + (size_t)n0 * D, g_wo_hi + (size_t)n0 * D, D,
              sb, t, C, false, false);

    const int g = lane >> 2, j2 = (lane & 3) * 2;
    const int wm = (wid >> 1) * 32, wn = (wid & 1) * 32;

    #pragma unroll
    for (int mi = 0; mi < 2; mi++) {
        const int mA = m0 + wm + mi * 16 + g;
        #pragma unroll
        for (int nt = 0; nt < 4; nt++) {
            const int n = n0 + wn + nt * 8 + j2;
            const float b0f = bo[n], b1f = bo[n + 1];
            float2 v0 = { C.a[mi][nt][0] + b0f, C.a[mi][nt][1] + b1f };
            float2 v1 = { C.a[mi][nt][2] + b0f, C.a[mi][nt][3] + b1f };
            *(float2*)(out + (size_t)mA * D + n) = v0;
            *(float2*)(out + (size_t)(mA + 8) * D + n) = v1;
        }
    }
}

// ======================= flash attention =======================
// 256 threads, 8 warps x 16 q-rows = 128-row q tile; kv chunks of 64, 32 chunks.
// S = QK^T: 2-product (qh*kh + qh*kl), restructured hi-pass then lo-pass
// (same-acc gap 8 instead of 2; per-acc order unchanged).  PV: 1-product.
#define A_STAGE 24576
#define A_KV    16384
__global__ __launch_bounds__(256, 2) void attn_kernel(const float* __restrict__ mask_all)
{
    extern __shared__ __align__(16) char smem[];
    const uint32_t sb = smem_u32(smem);

    const int q0 = blockIdx.x * 128;
    const int hb = blockIdx.y;
    const int h = hb / B, b = hb % B;

    const __half* Qh_g = g_qkvb_hi + ((size_t)0 * H + h) * BS * E + (size_t)(b * S + q0) * E;
    const __half* Kh_g = g_qkvb_hi + ((size_t)1 * H + h) * BS * E + (size_t)b * S * E;
    const __half* Kl_g = g_qkvb_lo + ((size_t)1 * H + h) * BS * E + (size_t)b * S * E;
    const __half* Vh_g = g_qkvb_hi + ((size_t)2 * H + h) * BS * E + (size_t)b * S * E;
    const float* mask = mask_all + (size_t)(h * B + b) * S * S;

    const int t = threadIdx.x, lane = t & 31, wid = t >> 5;
    const int g = lane >> 2, j2 = (lane & 3) * 2;
    const int r0 = wid * 16;

    // Q -> resident smem region (16K)
    cpa_tile<128>(Qh_g, E, sb, t);
    CP_COMMIT();
    // kv chunk 0 -> stage 0
    cpa_tile<64>(Kh_g, E, sb + A_KV, t);
    cpa_tile<64>(Kl_g, E, sb + A_KV + 8192, t);
    cpa_tile<64>(Vh_g, E, sb + A_KV + 16384, t);
    CP_COMMIT();

    float m_a = -INFINITY, m_b = -INFINITY, l_a = 0.f, l_b = 0.f;
    float o[8][4];
    #pragma unroll
    for (int et = 0; et < 8; et++)
        o[et][0] = o[et][1] = o[et][2] = o[et][3] = 0.f;

    const uint32_t a_row  = (uint32_t)(r0 + (lane & 15));
    const uint32_t a_chi  = (uint32_t)((lane >> 4) & 1);
    const uint32_t b_row0 = (uint32_t)((lane & 7) + ((lane & 16) >> 1));
    const uint32_t b_chi  = (uint32_t)((lane >> 3) & 1);
    const uint32_t v_row  = (uint32_t)(lane & 15);
    const uint32_t v_chi  = (uint32_t)((lane >> 4) & 1);

    #pragma unroll 1
    for (int jc = 0; jc < 32; jc++) {
        const int j0 = jc * 64;

        // mask loads initialize S accumulators; overlap pipeline wait
        float s[8][4];
        const float* mra = mask + (size_t)(q0 + r0 + g) * S + j0 + j2;
        const float* mrb = mra + 8 * S;
        #pragma unroll
        for (int nt = 0; nt < 8; nt++) {
            float2 ma = *(const float2*)(mra + nt * 8);
            float2 mb = *(const float2*)(mrb + nt * 8);
            s[nt][0] = ma.x; s[nt][1] = ma.y; s[nt][2] = mb.x; s[nt][3] = mb.y;
        }

        if (jc + 1 < 32) {
            const uint32_t ns = sb + A_KV + (uint32_t)((jc + 1) & 1) * A_STAGE;
            const size_t go = (size_t)(j0 + 64) * E;
            cpa_tile<64>(Kh_g + go, E, ns, t);
            cpa_tile<64>(Kl_g + go, E, ns + 8192, t);
            cpa_tile<64>(Vh_g + go, E, ns + 16384, t);
            CP_COMMIT();
            CP_WAIT1();
        } else {
            CP_WAIT0();
        }
        __syncthreads();

        const uint32_t cs = sb + A_KV + (uint32_t)(jc & 1) * A_STAGE;
        const uint32_t uKh = cs, uKl = cs + 8192, uVh = cs + 16384;

        // ---- S += Q K^T (2-product; hi pass over all np, then lo pass) ----
        #pragma unroll
        for (int ks = 0; ks < 4; ks++) {
            const uint32_t c16a = (uint32_t)(ks * 2) + a_chi;
            const uint32_t c16b = (uint32_t)(ks * 2) + b_chi;
            uint32_t qh[4];
            ldsm4(qh, sb + sw_off(a_row, c16a));
            // hi pass: 8 MMAs, 8 distinct accumulators
            #pragma unroll
            for (int np = 0; np < 4; np++) {
                uint32_t bh[4];
                ldsm4(bh, uKh + sw_off(b_row0 + np * 16, c16b));
                mma16816(s[2*np],   qh, bh[0], bh[1]);
                mma16816(s[2*np+1], qh, bh[2], bh[3]);
            }
            // lo pass: same 8 accumulators, gap 8
            #pragma unroll
            for (int np = 0; np < 4; np++) {
                uint32_t bl[4];
                ldsm4(bl, uKl + sw_off(b_row0 + np * 16, c16b));
                mma16816(s[2*np],   qh, bl[0], bl[1]);
                mma16816(s[2*np+1], qh, bl[2], bl[3]);
            }
        }

        // ---- online softmax (rows g and g+8) ----
        float mxa = -INFINITY, mxb = -INFINITY;
        #pragma unroll
        for (int nt = 0; nt < 8; nt++) {
            mxa = fmaxf(mxa, fmaxf(s[nt][0], s[nt][1]));
            mxb = fmaxf(mxb, fmaxf(s[nt][2], s[nt][3]));
        }
        mxa = fmaxf(mxa, __shfl_xor_sync(0xffffffffu, mxa, 1));
        mxa = fmaxf(mxa, __shfl_xor_sync(0xffffffffu, mxa, 2));
        mxb = fmaxf(mxb, __shfl_xor_sync(0xffffffffu, mxb, 1));
        mxb = fmaxf(mxb, __shfl_xor_sync(0xffffffffu, mxb, 2));

        const float mna = fmaxf(m_a, mxa), mnb = fmaxf(m_b, mxb);
        const float aa = __expf(m_a - mna), ab = __expf(m_b - mnb);
        float sa = 0.f, sb2 = 0.f;
        #pragma unroll
        for (int nt = 0; nt < 8; nt++) {
            s[nt][0] = __expf(s[nt][0] - mna); sa += s[nt][0];
            s[nt][1] = __expf(s[nt][1] - mna); sa += s[nt][1];
            s[nt][2] = __expf(s[nt][2] - mnb); sb2 += s[nt][2];
            s[nt][3] = __expf(s[nt][3] - mnb); sb2 += s[nt][3];
        }
        sa  += __shfl_xor_sync(0xffffffffu, sa, 1);
        sa  += __shfl_xor_sync(0xffffffffu, sa, 2);
        sb2 += __shfl_xor_sync(0xffffffffu, sb2, 1);
        sb2 += __shfl_xor_sync(0xffffffffu, sb2, 2);
        l_a = l_a * aa + sa; l_b = l_b * ab + sb2;
        m_a = mna; m_b = mnb;
        #pragma unroll
        for (int et = 0; et < 8; et++) {
            o[et][0] *= aa; o[et][1] *= aa;
            o[et][2] *= ab; o[et][3] *= ab;
        }

        // ---- O += P V (P plain fp16: 1-product; accs revisit gap 8) ----
        #pragma unroll
        for (int ks2 = 0; ks2 < 4; ks2++) {
            const int nt0 = 2 * ks2, nt1 = nt0 + 1;
            uint32_t a_p[4];
            a_p[0] = pack2(s[nt0][0], s[nt0][1]);
            a_p[1] = pack2(s[nt0][2], s[nt0][3]);
            a_p[2] = pack2(s[nt1][0], s[nt1][1]);
            a_p[3] = pack2(s[nt1][2], s[nt1][3]);
            #pragma unroll
            for (int ep = 0; ep < 4; ep++) {
                uint32_t vh[4];
                ldsm4t(vh, uVh + sw_off(v_row + ks2 * 16, (uint32_t)(ep * 2) + v_chi));
                mma16816(o[2*ep],   a_p, vh[0], vh[1]);
                mma16816(o[2*ep+1], a_p, vh[2], vh[3]);
            }
        }
        __syncthreads();
    }

    // ---- epilogue: normalize, pack fp16, concat-head layout ----
    const float ia = 1.f / l_a, ib = 1.f / l_b;
    const int rowA = q0 + r0 + g, rowB = rowA + 8;
    #pragma unroll
    for (int et = 0; et < 8; et++) {
        const size_t col = (size_t)h * E + et * 8 + j2;
        *(uint32_t*)(g_att_hi + (size_t)(b * S + rowA) * D + col) =
            pack2(o[et][0] * ia, o[et][1] * ia);
        *(uint32_t*)(g_att_hi + (size_t)(b * S + rowB) * D + col) =
            pack2(o[et][2] * ib, o[et][3] * ib);
    }
}

// ======================= Launch =======================
extern "C" void kernel_launch(void* const* d_in, const int* in_sizes, int n_in,
                              void* d_out, int out_size)
{
    const float* x    = (const float*)d_in[0];
    const float* mask = (const float*)d_in[1];
    const float* Wq   = (const float*)d_in[2];
    const float* bq   = (const float*)d_in[3];
    const float* Wk   = (const float*)d_in[4];
    const float* bk   = (const float*)d_in[5];
    const float* Wv   = (const float*)d_in[6];
    const float* bv   = (const float*)d_in[7];
    const float* Wo   = (const float*)d_in[8];
    const float* bo   = (const float*)d_in[9];

    const int smem_gemm = 2 * G_STAGE;          // 98,304 B
    const int smem_attn = A_KV + 2 * A_STAGE;   // 65,536 B
    cudaFuncSetAttribute(qkv_mma_kernel,  cudaFuncAttributeMaxDynamicSharedMemorySize, smem_gemm);
    cudaFuncSetAttribute(proj_mma_kernel, cudaFuncAttributeMaxDynamicSharedMemorySize, smem_gemm);
    cudaFuncSetAttribute(attn_kernel,     cudaFuncAttributeMaxDynamicSharedMemorySize, smem_attn);

    const int prep_n = XN + 3 * HED + D * D;
    prep_kernel<<< (prep_n + 255) / 256, 256 >>>(x, Wq, Wk, Wv, Wo);

    qkv_mma_kernel <<< dim3(BS / 128, 3 * H), 256, smem_gemm >>>(bq, bk, bv);
    attn_kernel    <<< dim3(S / 128, H * B), 256, smem_attn >>>(mask);
    proj_mma_kernel<<< dim3(BS / 128, D / 64), 256, smem_gemm >>>(bo, (float*)d_out);
}